// round 9
// baseline (speedup 1.0000x reference)
#include <cuda_runtime.h>

#define NND    100000
#define NEMAX  1600000
#define DIN    128
#define DH     256
#define NG     64
#define NC     16
#define NCHUNK 98   // ceil(100000/1024)

// ------------------------- scratch (device globals; no allocs) -------------
// NEVER passed as host-side kernel args (host sees only the shadow symbol!).
// All access is by name inside device code.
__device__ __align__(16) float g_mean[(size_t)NND * DH];
__device__ __align__(16) float g_h1  [(size_t)NND * DH];
__device__ __align__(16) float g_h2  [(size_t)NND * DH];
__device__ int   g_deg[NND];
__device__ int   g_rowstart[NND + 1];
__device__ int   g_cursor[NND];
__device__ int   g_srcs[NEMAX];
__device__ int   g_chunksum[NCHUNK + 1];
__device__ float g_pool[NG * DH];
__device__ int   g_cnt[NG];
__device__ int   g_ei64;   // 1 if edge_index is int64, 0 if int32
__device__ int   g_b64;    // 1 if batch is int64, 0 if int32

// --------------------------- decisive dtype probe ---------------------------
// Read candidate buffers AS int64 over the safe first half. int32 data seen as
// int64 gives lo + hi*2^32 with hi a live neighboring value -> out of range.
__global__ void detect_kernel(const void* __restrict__ ei,
                              const void* __restrict__ batch, int E, int NB) {
    if (threadIdx.x != 0 || blockIdx.x != 0) return;
    const long long* el = (const long long*)ei;
    const long long* bl = (const long long*)batch;
    int e64 = 1;
    for (int k = 0; k < 64; k++) {
        long long j = (long long)k * (E - 1) / 63;
        long long v = el[j];
        if (v < 0 || v >= NND) { e64 = 0; break; }
    }
    int b64 = 1;
    long long prev = -1;
    for (int k = 0; k < 64; k++) {
        long long j = (long long)k * (NB / 2 - 1) / 63;
        long long v = bl[j];
        if (v < 0 || v >= NG || v < prev) { b64 = 0; break; }
        prev = v;
    }
    g_ei64 = e64;
    g_b64  = b64;
}

__device__ __forceinline__ int idx_at(const void* p, long long i, int is64) {
    return is64 ? (int)((const long long*)p)[i] : ((const int*)p)[i];
}
__device__ __forceinline__ int clampi(int v, int lo, int hi) {
    return v < lo ? lo : (v > hi ? hi : v);
}

// ------------------------------ setup kernels ------------------------------
__global__ void zero_kernel() {
    int i = blockIdx.x * blockDim.x + threadIdx.x;
    if (i < NND)     g_deg[i] = 0;
    if (i < NG * DH) g_pool[i] = 0.f;
    if (i < NG)      g_cnt[i] = 0;
}

__global__ void count_deg_kernel(const void* __restrict__ ei, int E) {
    int e = blockIdx.x * blockDim.x + threadIdx.x;
    if (e >= E) return;
    int d = clampi(idx_at(ei, (long long)E + e, g_ei64), 0, NND - 1);
    atomicAdd(&g_deg[d], 1);
}

__global__ void scan_local_kernel() {
    __shared__ int s[1024];
    int b = blockIdx.x, tid = threadIdx.x;
    int i = b * 1024 + tid;
    int v = (i < NND) ? g_deg[i] : 0;
    s[tid] = v;
    for (int off = 1; off < 1024; off <<= 1) {
        __syncthreads();
        int t = (tid >= off) ? s[tid - off] : 0;
        __syncthreads();
        s[tid] += t;
    }
    __syncthreads();
    if (i < NND) g_rowstart[i] = s[tid] - v;       // exclusive within chunk
    if (tid == 1023) g_chunksum[b] = s[1023];
}

__global__ void scan_chunks_kernel() {
    if (threadIdx.x == 0 && blockIdx.x == 0) {
        int run = 0;
        for (int b = 0; b < NCHUNK; b++) {
            int t = g_chunksum[b];
            g_chunksum[b] = run;
            run += t;
        }
        g_rowstart[NND] = run;
    }
}

__global__ void add_offsets_kernel() {
    int i = blockIdx.x * blockDim.x + threadIdx.x;
    if (i < NND) {
        int v = g_rowstart[i] + g_chunksum[i >> 10];
        g_rowstart[i] = v;
        g_cursor[i]   = v;
    }
}

__global__ void fill_csr_kernel(const void* __restrict__ ei, int E) {
    int e = blockIdx.x * blockDim.x + threadIdx.x;
    if (e >= E) return;
    int is64 = g_ei64;
    int d = clampi(idx_at(ei, (long long)E + e, is64), 0, NND - 1);
    int s = clampi(idx_at(ei, (long long)e, is64), 0, NND - 1);
    int pos = atomicAdd(&g_cursor[d], 1);
    if ((unsigned)pos < NEMAX) g_srcs[pos] = s;
}

// --------------------- gather-based mean aggregation -----------------------
// LAYER 1: reads x (arg), D=128.  LAYER 2: reads g_h1 (by name), D=256.
// Output: g_mean (by name). One warp per destination node.
template <int LAYER>
__global__ void __launch_bounds__(256) agg_mean_kernel(const float* __restrict__ Xarg) {
    constexpr int D = (LAYER == 1) ? DIN : DH;
    const float* __restrict__ X = (LAYER == 1) ? Xarg : (const float*)g_h1;
    int warp = threadIdx.x >> 5;
    int lane = threadIdx.x & 31;
    int node = blockIdx.x * 8 + warp;
    if (node >= NND) return;
    int beg = g_rowstart[node];
    int end = g_rowstart[node + 1];
    float4 a0 = make_float4(0.f, 0.f, 0.f, 0.f);
    float4 a1 = make_float4(0.f, 0.f, 0.f, 0.f);
    for (int e = beg; e < end; e++) {
        int s = g_srcs[e];
        const float4* r = (const float4*)(X + (size_t)s * D) + lane;
        float4 v = r[0];
        a0.x += v.x; a0.y += v.y; a0.z += v.z; a0.w += v.w;
        if (D == 256) {
            float4 w = r[32];
            a1.x += w.x; a1.y += w.y; a1.z += w.z; a1.w += w.w;
        }
    }
    float sc = 1.f / fmaxf((float)(end - beg), 1.f);
    float4* o = (float4*)(g_mean + (size_t)node * D) + lane;
    a0.x *= sc; a0.y *= sc; a0.z *= sc; a0.w *= sc;
    o[0] = a0;
    if (D == 256) {
        a1.x *= sc; a1.y *= sc; a1.z *= sc; a1.w *= sc;
        o[32] = a1;
    }
}

// ------------------- fused dual SGEMM + bias + relu ------------------------
// C = relu(g_mean@Bl + X@Br + bias).  LAYER 1: X=x(arg), K=128, C=g_h1.
// LAYER 2: X=g_h1, K=256, C=g_h2. Scratch addressed by name only.
template <int LAYER>
__global__ void __launch_bounds__(256) gemm_dual_relu_kernel(
    const float* __restrict__ Xarg, const float* __restrict__ Bl,
    const float* __restrict__ Br, const float* __restrict__ bias) {
    constexpr int K = (LAYER == 1) ? DIN : DH;
    constexpr int M = NND;
    const float* __restrict__ A2 = (LAYER == 1) ? Xarg : (const float*)g_h1;
    float* __restrict__ C = (LAYER == 1) ? g_h1 : g_h2;

    __shared__ float Ats[8][128];
    __shared__ float Bs[8][128];
    int tid = threadIdx.x;
    int tx = tid & 15, ty = tid >> 4;
    int rowBase = blockIdx.y * 128;
    int colBase = blockIdx.x * 128;

    float acc[8][8];
    #pragma unroll
    for (int i = 0; i < 8; i++)
        #pragma unroll
        for (int j = 0; j < 8; j++) acc[i][j] = 0.f;

    int arow = tid >> 1;
    int acol = (tid & 1) * 4;
    int brow = tid >> 5;
    int bcol = (tid & 31) * 4;

    for (int p = 0; p < 2; p++) {
        const float* A = p ? A2 : (const float*)g_mean;
        const float* B = p ? Br : Bl;
        for (int k0 = 0; k0 < K; k0 += 8) {
            float4 av = make_float4(0.f, 0.f, 0.f, 0.f);
            int gr = rowBase + arow;
            if (gr < M) av = *(const float4*)(A + (size_t)gr * K + k0 + acol);
            float4 bv = *(const float4*)(B + (size_t)(k0 + brow) * DH + colBase + bcol);
            __syncthreads();
            Ats[acol + 0][arow] = av.x;
            Ats[acol + 1][arow] = av.y;
            Ats[acol + 2][arow] = av.z;
            Ats[acol + 3][arow] = av.w;
            *(float4*)&Bs[brow][bcol] = bv;
            __syncthreads();
            #pragma unroll
            for (int k = 0; k < 8; k++) {
                float ra[8], rb[8];
                #pragma unroll
                for (int i = 0; i < 8; i++) ra[i] = Ats[k][ty * 8 + i];
                #pragma unroll
                for (int j = 0; j < 8; j++) rb[j] = Bs[k][tx * 8 + j];
                #pragma unroll
                for (int i = 0; i < 8; i++)
                    #pragma unroll
                    for (int j = 0; j < 8; j++) acc[i][j] += ra[i] * rb[j];
            }
        }
    }
    #pragma unroll
    for (int i = 0; i < 8; i++) {
        int gr = rowBase + ty * 8 + i;
        if (gr >= M) continue;
        #pragma unroll
        for (int j = 0; j < 8; j++) {
            int gc = colBase + tx * 8 + j;
            float v = acc[i][j] + bias[gc];
            C[(size_t)gr * DH + gc] = v > 0.f ? v : 0.f;
        }
    }
}

// ----------------------- global mean pool (batch sorted) -------------------
__global__ void __launch_bounds__(256) pool_kernel(const void* __restrict__ batch) {
    __shared__ int sbatch[512];
    int base = blockIdx.x * 512;
    int c = threadIdx.x;               // column 0..255
    int is64 = g_b64;
    for (int j = threadIdx.x; j < 512; j += 256) {
        int idx = base + j;
        int g = -1;                     // -1 only marks past-the-end tail
        if (idx < NND) g = clampi(idx_at(batch, idx, is64), 0, NG - 1);
        sbatch[j] = g;
    }
    __syncthreads();
    float acc = 0.f;
    int cntl = 0;
    int cur = sbatch[0];
    for (int j = 0; j < 512; j++) {
        int g = sbatch[j];
        if (g != cur) {
            if (cur >= 0) {
                atomicAdd(&g_pool[cur * DH + c], acc);
                if (c == 0) atomicAdd(&g_cnt[cur], cntl);
            }
            acc = 0.f; cntl = 0; cur = g;
        }
        if (g < 0) break;
        acc += g_h2[(size_t)(base + j) * DH + c];
        cntl++;
    }
    if (cur >= 0) {
        atomicAdd(&g_pool[cur * DH + c], acc);
        if (c == 0) atomicAdd(&g_cnt[cur], cntl);
    }
}

__global__ void final_kernel(const float* __restrict__ fcW,
                             const float* __restrict__ fcb,
                             float* __restrict__ out) {
    int t = threadIdx.x;               // 1024 threads: 64 graphs x 16 classes
    int g = t >> 4;
    int cls = t & 15;
    float invc = 1.f / fmaxf((float)g_cnt[g], 1.f);
    float sum = fcb[cls];
    for (int k = 0; k < DH; k++)
        sum += g_pool[g * DH + k] * invc * fcW[k * NC + cls];
    out[g * NC + cls] = sum;
}

// -------------------------------- launch -----------------------------------
extern "C" void kernel_launch(void* const* d_in, const int* in_sizes, int n_in,
                              void* d_out, int out_size) {
    // ---- permutation-proof binding by element count ----
    const float *x = 0, *W1l = 0, *b1 = 0, *W1r = 0, *W2l = 0, *b2 = 0,
                *W2r = 0, *fcW = 0, *fcb = 0;
    const void *ei = 0, *batch = 0;
    int ei_elems = 2 * NEMAX;
    for (int i = 0; i < n_in; i++) {
        int s = in_sizes[i];
        const void* p = d_in[i];
        if (s == NND * DIN)            { x = (const float*)p; }
        else if (s == 2 * NEMAX)       { ei = p; ei_elems = s; }
        else if (s == NND)             { batch = p; }
        else if (s == DIN * DH)        { if (!W1l) W1l = (const float*)p; else W1r = (const float*)p; }
        else if (s == DH * DH)         { if (!W2l) W2l = (const float*)p; else W2r = (const float*)p; }
        else if (s == DH)              { if (!b1)  b1  = (const float*)p; else b2  = (const float*)p; }
        else if (s == DH * NC)         { fcW = (const float*)p; }
        else if (s == NC)              { fcb = (const float*)p; }
    }
    float* out = (float*)d_out;
    int E = ei_elems / 2;
    if (E > NEMAX) E = NEMAX;

    detect_kernel<<<1, 32>>>(ei, batch, E, NND);

    // build CSR (dst-indexed) + degrees
    zero_kernel<<<(NND + 255) / 256, 256>>>();
    count_deg_kernel<<<(E + 255) / 256, 256>>>(ei, E);
    scan_local_kernel<<<NCHUNK, 1024>>>();
    scan_chunks_kernel<<<1, 32>>>();
    add_offsets_kernel<<<(NND + 255) / 256, 256>>>();
    fill_csr_kernel<<<(E + 255) / 256, 256>>>(ei, E);

    dim3 ggrid(DH / 128, (NND + 127) / 128);

    // layer 1
    agg_mean_kernel<1><<<(NND + 7) / 8, 256>>>(x);
    gemm_dual_relu_kernel<1><<<ggrid, 256>>>(x, W1l, W1r, b1);

    // layer 2
    agg_mean_kernel<2><<<(NND + 7) / 8, 256>>>(x);
    gemm_dual_relu_kernel<2><<<ggrid, 256>>>(x, W2l, W2r, b2);

    // pool + classifier
    pool_kernel<<<(NND + 511) / 512, 256>>>(batch);
    final_kernel<<<1, 1024>>>(fcW, fcb, out);
}

// round 10
// speedup vs baseline: 1.0480x; 1.0480x over previous
#include <cuda_runtime.h>

#define NND    100000
#define NEMAX  1600000
#define DIN    128
#define DH     256
#define NG     64
#define NC     16
#define NCHUNK 98   // ceil(100000/1024)

// ------------------------- scratch (device globals; no allocs) -------------
// NEVER passed as host-side kernel args. Accessed by name inside device code.
__device__ __align__(16) float g_mean[(size_t)NND * DH];
__device__ __align__(16) float g_h1  [(size_t)NND * DH];
__device__ __align__(16) float g_h2  [(size_t)NND * DH];
__device__ int   g_deg[NND];
__device__ int   g_rowstart[NND + 1];
__device__ int   g_cursor[NND];
__device__ int   g_srcs[NEMAX];
__device__ int   g_chunksum[NCHUNK + 1];
__device__ float g_pool[NG * DH];
__device__ int   g_cnt[NG];
__device__ int   g_ei64;
__device__ int   g_b64;

// --------------------------- packed f32x2 helpers ---------------------------
__device__ __forceinline__ unsigned long long fma2(unsigned long long a,
                                                   unsigned long long b,
                                                   unsigned long long c) {
    unsigned long long d;
    asm("fma.rn.f32x2 %0, %1, %2, %3;" : "=l"(d) : "l"(a), "l"(b), "l"(c));
    return d;
}
__device__ __forceinline__ unsigned long long dup2(float a) {
    unsigned long long d;
    asm("mov.b64 %0, {%1, %1};" : "=l"(d) : "f"(a));
    return d;
}
__device__ __forceinline__ float2 unpack2(unsigned long long v) {
    float lo, hi;
    asm("mov.b64 {%0, %1}, %2;" : "=f"(lo), "=f"(hi) : "l"(v));
    return make_float2(lo, hi);
}

// --------------------------- decisive dtype probe ---------------------------
__global__ void detect_kernel(const void* __restrict__ ei,
                              const void* __restrict__ batch, int E, int NB) {
    if (threadIdx.x != 0 || blockIdx.x != 0) return;
    const long long* el = (const long long*)ei;
    const long long* bl = (const long long*)batch;
    int e64 = 1;
    for (int k = 0; k < 64; k++) {
        long long j = (long long)k * (E - 1) / 63;
        long long v = el[j];
        if (v < 0 || v >= NND) { e64 = 0; break; }
    }
    int b64 = 1;
    long long prev = -1;
    for (int k = 0; k < 64; k++) {
        long long j = (long long)k * (NB / 2 - 1) / 63;
        long long v = bl[j];
        if (v < 0 || v >= NG || v < prev) { b64 = 0; break; }
        prev = v;
    }
    g_ei64 = e64;
    g_b64  = b64;
}

__device__ __forceinline__ int idx_at(const void* p, long long i, int is64) {
    return is64 ? (int)((const long long*)p)[i] : ((const int*)p)[i];
}
__device__ __forceinline__ int clampi(int v, int lo, int hi) {
    return v < lo ? lo : (v > hi ? hi : v);
}

// ------------------------------ setup kernels ------------------------------
__global__ void zero_kernel() {
    int i = blockIdx.x * blockDim.x + threadIdx.x;
    if (i < NND)     g_deg[i] = 0;
    if (i < NG * DH) g_pool[i] = 0.f;
    if (i < NG)      g_cnt[i] = 0;
}

__global__ void count_deg_kernel(const void* __restrict__ ei, int E) {
    int e = blockIdx.x * blockDim.x + threadIdx.x;
    if (e >= E) return;
    int d = clampi(idx_at(ei, (long long)E + e, g_ei64), 0, NND - 1);
    atomicAdd(&g_deg[d], 1);
}

__global__ void scan_local_kernel() {
    __shared__ int s[1024];
    int b = blockIdx.x, tid = threadIdx.x;
    int i = b * 1024 + tid;
    int v = (i < NND) ? g_deg[i] : 0;
    s[tid] = v;
    for (int off = 1; off < 1024; off <<= 1) {
        __syncthreads();
        int t = (tid >= off) ? s[tid - off] : 0;
        __syncthreads();
        s[tid] += t;
    }
    __syncthreads();
    if (i < NND) g_rowstart[i] = s[tid] - v;
    if (tid == 1023) g_chunksum[b] = s[1023];
}

__global__ void scan_chunks_kernel() {
    if (threadIdx.x == 0 && blockIdx.x == 0) {
        int run = 0;
        for (int b = 0; b < NCHUNK; b++) {
            int t = g_chunksum[b];
            g_chunksum[b] = run;
            run += t;
        }
        g_rowstart[NND] = run;
    }
}

__global__ void add_offsets_kernel() {
    int i = blockIdx.x * blockDim.x + threadIdx.x;
    if (i < NND) {
        int v = g_rowstart[i] + g_chunksum[i >> 10];
        g_rowstart[i] = v;
        g_cursor[i]   = v;
    }
}

__global__ void fill_csr_kernel(const void* __restrict__ ei, int E) {
    int e = blockIdx.x * blockDim.x + threadIdx.x;
    if (e >= E) return;
    int is64 = g_ei64;
    int d = clampi(idx_at(ei, (long long)E + e, is64), 0, NND - 1);
    int s = clampi(idx_at(ei, (long long)e, is64), 0, NND - 1);
    int pos = atomicAdd(&g_cursor[d], 1);
    if ((unsigned)pos < NEMAX) g_srcs[pos] = s;
}

// --------------------- gather-based mean aggregation -----------------------
template <int LAYER>
__global__ void __launch_bounds__(256) agg_mean_kernel(const float* __restrict__ Xarg) {
    constexpr int D = (LAYER == 1) ? DIN : DH;
    const float* __restrict__ X = (LAYER == 1) ? Xarg : (const float*)g_h1;
    int warp = threadIdx.x >> 5;
    int lane = threadIdx.x & 31;
    int node = blockIdx.x * 8 + warp;
    if (node >= NND) return;
    int beg = g_rowstart[node];
    int end = g_rowstart[node + 1];
    float4 a0 = make_float4(0.f, 0.f, 0.f, 0.f);
    float4 a1 = make_float4(0.f, 0.f, 0.f, 0.f);
    for (int e = beg; e < end; e++) {
        int s = g_srcs[e];
        const float4* r = (const float4*)(X + (size_t)s * D) + lane;
        float4 v = r[0];
        a0.x += v.x; a0.y += v.y; a0.z += v.z; a0.w += v.w;
        if (D == 256) {
            float4 w = r[32];
            a1.x += w.x; a1.y += w.y; a1.z += w.z; a1.w += w.w;
        }
    }
    float sc = 1.f / fmaxf((float)(end - beg), 1.f);
    float4* o = (float4*)(g_mean + (size_t)node * D) + lane;
    a0.x *= sc; a0.y *= sc; a0.z *= sc; a0.w *= sc;
    o[0] = a0;
    if (D == 256) {
        a1.x *= sc; a1.y *= sc; a1.z *= sc; a1.w *= sc;
        o[32] = a1;
    }
}

// ------------- fused dual SGEMM + bias + relu, packed f32x2 ----------------
// C = relu(g_mean@Bl + X@Br + bias).  LAYER 1: X=x(arg), K=128, C=g_h1.
// LAYER 2: X=g_h1, K=256, C=g_h2.
template <int LAYER>
__global__ void __launch_bounds__(256) gemm_dual_relu_kernel(
    const float* __restrict__ Xarg, const float* __restrict__ Bl,
    const float* __restrict__ Br, const float* __restrict__ bias) {
    constexpr int K = (LAYER == 1) ? DIN : DH;
    constexpr int M = NND;
    const float* __restrict__ A2 = (LAYER == 1) ? Xarg : (const float*)g_h1;
    float* __restrict__ C = (LAYER == 1) ? g_h1 : g_h2;

    __shared__ float Ats[8][128];
    __shared__ float Bs[8][128];
    int tid = threadIdx.x;
    int tx = tid & 15, ty = tid >> 4;
    int rowBase = blockIdx.y * 128;
    int colBase = blockIdx.x * 128;

    // acc2[i][jp] holds C[i][2jp], C[i][2jp+1] packed
    unsigned long long acc2[8][4];
    #pragma unroll
    for (int i = 0; i < 8; i++)
        #pragma unroll
        for (int j = 0; j < 4; j++) acc2[i][j] = 0ull;

    int arow = tid >> 1;
    int acol = (tid & 1) * 4;
    int brow = tid >> 5;
    int bcol = (tid & 31) * 4;

    for (int p = 0; p < 2; p++) {
        const float* A = p ? A2 : (const float*)g_mean;
        const float* B = p ? Br : Bl;
        for (int k0 = 0; k0 < K; k0 += 8) {
            float4 av = make_float4(0.f, 0.f, 0.f, 0.f);
            int gr = rowBase + arow;
            if (gr < M) av = *(const float4*)(A + (size_t)gr * K + k0 + acol);
            float4 bv = *(const float4*)(B + (size_t)(k0 + brow) * DH + colBase + bcol);
            __syncthreads();
            Ats[acol + 0][arow] = av.x;
            Ats[acol + 1][arow] = av.y;
            Ats[acol + 2][arow] = av.z;
            Ats[acol + 3][arow] = av.w;
            *(float4*)&Bs[brow][bcol] = bv;
            __syncthreads();
            #pragma unroll
            for (int k = 0; k < 8; k++) {
                float4 ra0 = *(const float4*)&Ats[k][ty * 8];
                float4 ra1 = *(const float4*)&Ats[k][ty * 8 + 4];
                const ulonglong2* bp = (const ulonglong2*)&Bs[k][tx * 8];
                ulonglong2 rb01 = bp[0];
                ulonglong2 rb23 = bp[1];
                unsigned long long ad[8];
                ad[0] = dup2(ra0.x); ad[1] = dup2(ra0.y);
                ad[2] = dup2(ra0.z); ad[3] = dup2(ra0.w);
                ad[4] = dup2(ra1.x); ad[5] = dup2(ra1.y);
                ad[6] = dup2(ra1.z); ad[7] = dup2(ra1.w);
                #pragma unroll
                for (int i = 0; i < 8; i++) {
                    acc2[i][0] = fma2(ad[i], rb01.x, acc2[i][0]);
                    acc2[i][1] = fma2(ad[i], rb01.y, acc2[i][1]);
                    acc2[i][2] = fma2(ad[i], rb23.x, acc2[i][2]);
                    acc2[i][3] = fma2(ad[i], rb23.y, acc2[i][3]);
                }
            }
        }
    }
    #pragma unroll
    for (int i = 0; i < 8; i++) {
        int gr = rowBase + ty * 8 + i;
        if (gr >= M) continue;
        #pragma unroll
        for (int jp = 0; jp < 4; jp++) {
            int gc = colBase + tx * 8 + jp * 2;
            float2 v = unpack2(acc2[i][jp]);
            float v0 = v.x + bias[gc];
            float v1 = v.y + bias[gc + 1];
            float2 o;
            o.x = v0 > 0.f ? v0 : 0.f;
            o.y = v1 > 0.f ? v1 : 0.f;
            *(float2*)&C[(size_t)gr * DH + gc] = o;
        }
    }
}

// ----------------------- global mean pool (batch sorted) -------------------
__global__ void __launch_bounds__(256) pool_kernel(const void* __restrict__ batch) {
    __shared__ int sbatch[512];
    int base = blockIdx.x * 512;
    int c = threadIdx.x;               // column 0..255
    int is64 = g_b64;
    for (int j = threadIdx.x; j < 512; j += 256) {
        int idx = base + j;
        int g = -1;
        if (idx < NND) g = clampi(idx_at(batch, idx, is64), 0, NG - 1);
        sbatch[j] = g;
    }
    __syncthreads();
    float acc = 0.f;
    int cntl = 0;
    int cur = sbatch[0];
    for (int j = 0; j < 512; j++) {
        int g = sbatch[j];
        if (g != cur) {
            if (cur >= 0) {
                atomicAdd(&g_pool[cur * DH + c], acc);
                if (c == 0) atomicAdd(&g_cnt[cur], cntl);
            }
            acc = 0.f; cntl = 0; cur = g;
        }
        if (g < 0) break;
        acc += g_h2[(size_t)(base + j) * DH + c];
        cntl++;
    }
    if (cur >= 0) {
        atomicAdd(&g_pool[cur * DH + c], acc);
        if (c == 0) atomicAdd(&g_cnt[cur], cntl);
    }
}

__global__ void final_kernel(const float* __restrict__ fcW,
                             const float* __restrict__ fcb,
                             float* __restrict__ out) {
    int t = threadIdx.x;               // 1024 threads: 64 graphs x 16 classes
    int g = t >> 4;
    int cls = t & 15;
    float invc = 1.f / fmaxf((float)g_cnt[g], 1.f);
    float sum = fcb[cls];
    for (int k = 0; k < DH; k++)
        sum += g_pool[g * DH + k] * invc * fcW[k * NC + cls];
    out[g * NC + cls] = sum;
}

// -------------------------------- launch -----------------------------------
extern "C" void kernel_launch(void* const* d_in, const int* in_sizes, int n_in,
                              void* d_out, int out_size) {
    const float *x = 0, *W1l = 0, *b1 = 0, *W1r = 0, *W2l = 0, *b2 = 0,
                *W2r = 0, *fcW = 0, *fcb = 0;
    const void *ei = 0, *batch = 0;
    int ei_elems = 2 * NEMAX;
    for (int i = 0; i < n_in; i++) {
        int s = in_sizes[i];
        const void* p = d_in[i];
        if (s == NND * DIN)            { x = (const float*)p; }
        else if (s == 2 * NEMAX)       { ei = p; ei_elems = s; }
        else if (s == NND)             { batch = p; }
        else if (s == DIN * DH)        { if (!W1l) W1l = (const float*)p; else W1r = (const float*)p; }
        else if (s == DH * DH)         { if (!W2l) W2l = (const float*)p; else W2r = (const float*)p; }
        else if (s == DH)              { if (!b1)  b1  = (const float*)p; else b2  = (const float*)p; }
        else if (s == DH * NC)         { fcW = (const float*)p; }
        else if (s == NC)              { fcb = (const float*)p; }
    }
    float* out = (float*)d_out;
    int E = ei_elems / 2;
    if (E > NEMAX) E = NEMAX;

    detect_kernel<<<1, 32>>>(ei, batch, E, NND);

    zero_kernel<<<(NND + 255) / 256, 256>>>();
    count_deg_kernel<<<(E + 255) / 256, 256>>>(ei, E);
    scan_local_kernel<<<NCHUNK, 1024>>>();
    scan_chunks_kernel<<<1, 32>>>();
    add_offsets_kernel<<<(NND + 255) / 256, 256>>>();
    fill_csr_kernel<<<(E + 255) / 256, 256>>>(ei, E);

    dim3 ggrid(DH / 128, (NND + 127) / 128);

    agg_mean_kernel<1><<<(NND + 7) / 8, 256>>>(x);
    gemm_dual_relu_kernel<1><<<ggrid, 256>>>(x, W1l, W1r, b1);

    agg_mean_kernel<2><<<(NND + 7) / 8, 256>>>(x);
    gemm_dual_relu_kernel<2><<<ggrid, 256>>>(x, W2l, W2r, b2);

    pool_kernel<<<(NND + 511) / 512, 256>>>(batch);
    final_kernel<<<1, 1024>>>(fcW, fcb, out);
}

// round 11
// speedup vs baseline: 1.2663x; 1.2083x over previous
#include <cuda_runtime.h>
#include <cuda_bf16.h>
#include <mma.h>

using namespace nvcuda;

#define NND    100000
#define NEMAX  1600000
#define DIN    128
#define DH     256
#define NG     64
#define NC     16
#define NCHUNK 98   // ceil(100000/1024)

// ------------------------- scratch (device globals; no allocs) -------------
// NEVER passed as host-side kernel args. Accessed by name inside device code.
__device__ __align__(16) float g_h1[(size_t)NND * DH];
__device__ __align__(16) float g_h2[(size_t)NND * DH];
__device__ __align__(16) __nv_bfloat16 g_mhi[(size_t)NND * DH];
__device__ __align__(16) __nv_bfloat16 g_mlo[(size_t)NND * DH];
__device__ __align__(16) __nv_bfloat16 g_xhi[(size_t)NND * DIN];
__device__ __align__(16) __nv_bfloat16 g_xlo[(size_t)NND * DIN];
__device__ __align__(16) __nv_bfloat16 g_h1hi[(size_t)NND * DH];
__device__ __align__(16) __nv_bfloat16 g_h1lo[(size_t)NND * DH];
__device__ __align__(16) __nv_bfloat16 g_wlhi[DH * DH];
__device__ __align__(16) __nv_bfloat16 g_wllo[DH * DH];
__device__ __align__(16) __nv_bfloat16 g_wrhi[DH * DH];
__device__ __align__(16) __nv_bfloat16 g_wrlo[DH * DH];
__device__ int   g_deg[NND];
__device__ int   g_rowstart[NND + 1];
__device__ int   g_cursor[NND];
__device__ int   g_srcs[NEMAX];
__device__ int   g_chunksum[NCHUNK + 1];
__device__ float g_pool[NG * DH];
__device__ int   g_cnt[NG];
__device__ int   g_ei64;
__device__ int   g_b64;

// --------------------------- helpers ---------------------------------------
__device__ __forceinline__ void split_bf16(float v, __nv_bfloat16& hi, __nv_bfloat16& lo) {
    hi = __float2bfloat16(v);
    lo = __float2bfloat16(v - __bfloat162float(hi));
}
__device__ __forceinline__ unsigned pack2(__nv_bfloat16 a, __nv_bfloat16 b) {
    __nv_bfloat162 t; t.x = a; t.y = b;
    return *(unsigned*)&t;
}
__device__ __forceinline__ int idx_at(const void* p, long long i, int is64) {
    return is64 ? (int)((const long long*)p)[i] : ((const int*)p)[i];
}
__device__ __forceinline__ int clampi(int v, int lo, int hi) {
    return v < lo ? lo : (v > hi ? hi : v);
}

// --------------------------- decisive dtype probe ---------------------------
__global__ void detect_kernel(const void* __restrict__ ei,
                              const void* __restrict__ batch, int E, int NB) {
    if (threadIdx.x != 0 || blockIdx.x != 0) return;
    const long long* el = (const long long*)ei;
    const long long* bl = (const long long*)batch;
    int e64 = 1;
    for (int k = 0; k < 64; k++) {
        long long j = (long long)k * (E - 1) / 63;
        long long v = el[j];
        if (v < 0 || v >= NND) { e64 = 0; break; }
    }
    int b64 = 1;
    long long prev = -1;
    for (int k = 0; k < 64; k++) {
        long long j = (long long)k * (NB / 2 - 1) / 63;
        long long v = bl[j];
        if (v < 0 || v >= NG || v < prev) { b64 = 0; break; }
        prev = v;
    }
    g_ei64 = e64;
    g_b64  = b64;
}

// ------------------------------ setup kernels ------------------------------
__global__ void zero_kernel() {
    int i = blockIdx.x * blockDim.x + threadIdx.x;
    if (i < NND)     g_deg[i] = 0;
    if (i < NG * DH) g_pool[i] = 0.f;
    if (i < NG)      g_cnt[i] = 0;
}

__global__ void count_deg_kernel(const void* __restrict__ ei, int E) {
    int e = blockIdx.x * blockDim.x + threadIdx.x;
    if (e >= E) return;
    int d = clampi(idx_at(ei, (long long)E + e, g_ei64), 0, NND - 1);
    atomicAdd(&g_deg[d], 1);
}

__global__ void scan_local_kernel() {
    __shared__ int s[1024];
    int b = blockIdx.x, tid = threadIdx.x;
    int i = b * 1024 + tid;
    int v = (i < NND) ? g_deg[i] : 0;
    s[tid] = v;
    for (int off = 1; off < 1024; off <<= 1) {
        __syncthreads();
        int t = (tid >= off) ? s[tid - off] : 0;
        __syncthreads();
        s[tid] += t;
    }
    __syncthreads();
    if (i < NND) g_rowstart[i] = s[tid] - v;
    if (tid == 1023) g_chunksum[b] = s[1023];
}

__global__ void scan_chunks_kernel() {
    if (threadIdx.x == 0 && blockIdx.x == 0) {
        int run = 0;
        for (int b = 0; b < NCHUNK; b++) {
            int t = g_chunksum[b];
            g_chunksum[b] = run;
            run += t;
        }
        g_rowstart[NND] = run;
    }
}

__global__ void add_offsets_kernel() {
    int i = blockIdx.x * blockDim.x + threadIdx.x;
    if (i < NND) {
        int v = g_rowstart[i] + g_chunksum[i >> 10];
        g_rowstart[i] = v;
        g_cursor[i]   = v;
    }
}

__global__ void fill_csr_kernel(const void* __restrict__ ei, int E) {
    int e = blockIdx.x * blockDim.x + threadIdx.x;
    if (e >= E) return;
    int is64 = g_ei64;
    int d = clampi(idx_at(ei, (long long)E + e, is64), 0, NND - 1);
    int s = clampi(idx_at(ei, (long long)e, is64), 0, NND - 1);
    int pos = atomicAdd(&g_cursor[d], 1);
    if ((unsigned)pos < NEMAX) g_srcs[pos] = s;
}

// ----------------------- input / weight conversion -------------------------
__global__ void convert_x_kernel(const float* __restrict__ X) {
    int i = blockIdx.x * blockDim.x + threadIdx.x;   // one float4 per thread
    if (i >= NND * DIN / 4) return;
    float4 v = ((const float4*)X)[i];
    __nv_bfloat16 h0, h1, h2, h3, l0, l1, l2, l3;
    split_bf16(v.x, h0, l0); split_bf16(v.y, h1, l1);
    split_bf16(v.z, h2, l2); split_bf16(v.w, h3, l3);
    uint2 uh; uh.x = pack2(h0, h1); uh.y = pack2(h2, h3);
    uint2 ul; ul.x = pack2(l0, l1); ul.y = pack2(l2, l3);
    ((uint2*)g_xhi)[i] = uh;
    ((uint2*)g_xlo)[i] = ul;
}

__global__ void convert_w_kernel(const float* __restrict__ Bl,
                                 const float* __restrict__ Br, int K) {
    int i = blockIdx.x * blockDim.x + threadIdx.x;
    if (i >= K * DH) return;
    __nv_bfloat16 hi, lo;
    split_bf16(Bl[i], hi, lo);
    g_wlhi[i] = hi; g_wllo[i] = lo;
    split_bf16(Br[i], hi, lo);
    g_wrhi[i] = hi; g_wrlo[i] = lo;
}

// --------------------- gather-based mean aggregation -----------------------
// Writes split bf16 means to g_mhi/g_mlo. One warp per destination node.
template <int LAYER>
__global__ void __launch_bounds__(256) agg_mean_kernel(const float* __restrict__ Xarg) {
    constexpr int D = (LAYER == 1) ? DIN : DH;
    const float* __restrict__ X = (LAYER == 1) ? Xarg : (const float*)g_h1;
    int warp = threadIdx.x >> 5;
    int lane = threadIdx.x & 31;
    int node = blockIdx.x * 8 + warp;
    if (node >= NND) return;
    int beg = g_rowstart[node];
    int end = g_rowstart[node + 1];
    float4 a0 = make_float4(0.f, 0.f, 0.f, 0.f);
    float4 a1 = make_float4(0.f, 0.f, 0.f, 0.f);
    for (int e = beg; e < end; e++) {
        int s = g_srcs[e];
        const float4* r = (const float4*)(X + (size_t)s * D) + lane;
        float4 v = r[0];
        a0.x += v.x; a0.y += v.y; a0.z += v.z; a0.w += v.w;
        if (D == 256) {
            float4 w = r[32];
            a1.x += w.x; a1.y += w.y; a1.z += w.z; a1.w += w.w;
        }
    }
    float sc = 1.f / fmaxf((float)(end - beg), 1.f);
    {
        __nv_bfloat16 h0, h1, h2, h3, l0, l1, l2, l3;
        split_bf16(a0.x * sc, h0, l0); split_bf16(a0.y * sc, h1, l1);
        split_bf16(a0.z * sc, h2, l2); split_bf16(a0.w * sc, h3, l3);
        uint2 uh; uh.x = pack2(h0, h1); uh.y = pack2(h2, h3);
        uint2 ul; ul.x = pack2(l0, l1); ul.y = pack2(l2, l3);
        *(uint2*)(g_mhi + (size_t)node * D + lane * 4) = uh;
        *(uint2*)(g_mlo + (size_t)node * D + lane * 4) = ul;
    }
    if (D == 256) {
        __nv_bfloat16 h0, h1, h2, h3, l0, l1, l2, l3;
        split_bf16(a1.x * sc, h0, l0); split_bf16(a1.y * sc, h1, l1);
        split_bf16(a1.z * sc, h2, l2); split_bf16(a1.w * sc, h3, l3);
        uint2 uh; uh.x = pack2(h0, h1); uh.y = pack2(h2, h3);
        uint2 ul; ul.x = pack2(l0, l1); ul.y = pack2(l2, l3);
        *(uint2*)(g_mhi + (size_t)node * D + 128 + lane * 4) = uh;
        *(uint2*)(g_mlo + (size_t)node * D + 128 + lane * 4) = ul;
    }
}

// ----------- dual GEMM + bias + relu via bf16-split tensor cores -----------
// C = relu(mean@Bl + X@Br + bias), computed as 6 accumulating K-passes:
// (mhi,Blhi) (mhi,Bllo) (mlo,Blhi) (Xhi,Brhi) (Xhi,Brlo) (Xlo,Brhi)
// Block: 128x128 output, 8 warps (2x4), warp tile 64x32 (4x2 wmma frags).
#define LDA 40
#define LDB 136
template <int LAYER>
__global__ void __launch_bounds__(256) gemm_wmma_kernel(const float* __restrict__ bias) {
    constexpr int K = (LAYER == 1) ? DIN : DH;
    const __nv_bfloat16* Xhi = (LAYER == 1) ? g_xhi : g_h1hi;
    const __nv_bfloat16* Xlo = (LAYER == 1) ? g_xlo : g_h1lo;
    const __nv_bfloat16* APass[6] = { g_mhi, g_mhi, g_mlo, Xhi,   Xhi,   Xlo   };
    const __nv_bfloat16* BPass[6] = { g_wlhi, g_wllo, g_wlhi, g_wrhi, g_wrlo, g_wrhi };

    __shared__ __nv_bfloat16 As[128 * LDA];
    __shared__ __nv_bfloat16 Bs[32 * LDB];
    __shared__ float Epi[8 * 256];

    int tid = threadIdx.x;
    int wid = tid >> 5, lane = tid & 31;
    int warpRow = wid >> 2, warpCol = wid & 3;
    int rowBase = blockIdx.y * 128;
    int colBase = blockIdx.x * 128;

    wmma::fragment<wmma::accumulator, 16, 16, 16, float> acc[4][2];
    #pragma unroll
    for (int i = 0; i < 4; i++)
        #pragma unroll
        for (int j = 0; j < 2; j++) wmma::fill_fragment(acc[i][j], 0.f);

    int arow = tid >> 1, ahalf = tid & 1;          // A: 128 rows x 32 cols
    int brow = tid >> 3, bseg = (tid & 7) * 16;    // B: 32 rows x 128 cols

    for (int p = 0; p < 6; p++) {
        const __nv_bfloat16* A = APass[p];
        const __nv_bfloat16* B = BPass[p];
        for (int k0 = 0; k0 < K; k0 += 32) {
            uint4 z = make_uint4(0, 0, 0, 0);
            uint4 a0 = z, a1 = z;
            int gr = rowBase + arow;
            if (gr < NND) {
                const uint4* src = (const uint4*)(A + (size_t)gr * K + k0 + ahalf * 16);
                a0 = src[0]; a1 = src[1];
            }
            uint4 b0, b1;
            {
                const uint4* src = (const uint4*)(B + (size_t)(k0 + brow) * DH + colBase + bseg);
                b0 = src[0]; b1 = src[1];
            }
            __syncthreads();
            {
                uint4* d = (uint4*)(As + arow * LDA + ahalf * 16);
                d[0] = a0; d[1] = a1;
                uint4* bd = (uint4*)(Bs + brow * LDB + bseg);
                bd[0] = b0; bd[1] = b1;
            }
            __syncthreads();
            #pragma unroll
            for (int kf = 0; kf < 2; kf++) {
                wmma::fragment<wmma::matrix_a, 16, 16, 16, __nv_bfloat16, wmma::row_major> af[4];
                #pragma unroll
                for (int i = 0; i < 4; i++)
                    wmma::load_matrix_sync(af[i], As + (warpRow * 64 + i * 16) * LDA + kf * 16, LDA);
                wmma::fragment<wmma::matrix_b, 16, 16, 16, __nv_bfloat16, wmma::row_major> bf[2];
                #pragma unroll
                for (int j = 0; j < 2; j++)
                    wmma::load_matrix_sync(bf[j], Bs + (kf * 16) * LDB + warpCol * 32 + j * 16, LDB);
                #pragma unroll
                for (int i = 0; i < 4; i++)
                    #pragma unroll
                    for (int j = 0; j < 2; j++)
                        wmma::mma_sync(acc[i][j], af[i], bf[j], acc[i][j]);
            }
        }
    }

    // epilogue: one 16x16 fragment at a time through per-warp smem staging
    float* buf = Epi + wid * 256;
    #pragma unroll
    for (int i = 0; i < 4; i++) {
        #pragma unroll
        for (int j = 0; j < 2; j++) {
            wmma::store_matrix_sync(buf, acc[i][j], 16, wmma::mem_row_major);
            __syncwarp();
            #pragma unroll
            for (int e = 0; e < 8; e++) {
                int idx = e * 32 + lane;
                int r = idx >> 4, c = idx & 15;
                int gr = rowBase + warpRow * 64 + i * 16 + r;
                int gc = colBase + warpCol * 32 + j * 16 + c;
                if (gr < NND) {
                    float v = buf[r * 16 + c] + bias[gc];
                    v = v > 0.f ? v : 0.f;
                    if (LAYER == 1) {
                        g_h1[(size_t)gr * DH + gc] = v;
                        __nv_bfloat16 hi, lo;
                        split_bf16(v, hi, lo);
                        g_h1hi[(size_t)gr * DH + gc] = hi;
                        g_h1lo[(size_t)gr * DH + gc] = lo;
                    } else {
                        g_h2[(size_t)gr * DH + gc] = v;
                    }
                }
            }
            __syncwarp();
        }
    }
}

// ----------------------- global mean pool (batch sorted) -------------------
__global__ void __launch_bounds__(256) pool_kernel(const void* __restrict__ batch) {
    __shared__ int sbatch[512];
    int base = blockIdx.x * 512;
    int c = threadIdx.x;
    int is64 = g_b64;
    for (int j = threadIdx.x; j < 512; j += 256) {
        int idx = base + j;
        int g = -1;
        if (idx < NND) g = clampi(idx_at(batch, idx, is64), 0, NG - 1);
        sbatch[j] = g;
    }
    __syncthreads();
    float acc = 0.f;
    int cntl = 0;
    int cur = sbatch[0];
    for (int j = 0; j < 512; j++) {
        int g = sbatch[j];
        if (g != cur) {
            if (cur >= 0) {
                atomicAdd(&g_pool[cur * DH + c], acc);
                if (c == 0) atomicAdd(&g_cnt[cur], cntl);
            }
            acc = 0.f; cntl = 0; cur = g;
        }
        if (g < 0) break;
        acc += g_h2[(size_t)(base + j) * DH + c];
        cntl++;
    }
    if (cur >= 0) {
        atomicAdd(&g_pool[cur * DH + c], acc);
        if (c == 0) atomicAdd(&g_cnt[cur], cntl);
    }
}

__global__ void final_kernel(const float* __restrict__ fcW,
                             const float* __restrict__ fcb,
                             float* __restrict__ out) {
    int t = threadIdx.x;
    int g = t >> 4;
    int cls = t & 15;
    float invc = 1.f / fmaxf((float)g_cnt[g], 1.f);
    float sum = fcb[cls];
    for (int k = 0; k < DH; k++)
        sum += g_pool[g * DH + k] * invc * fcW[k * NC + cls];
    out[g * NC + cls] = sum;
}

// -------------------------------- launch -----------------------------------
extern "C" void kernel_launch(void* const* d_in, const int* in_sizes, int n_in,
                              void* d_out, int out_size) {
    const float *x = 0, *W1l = 0, *b1 = 0, *W1r = 0, *W2l = 0, *b2 = 0,
                *W2r = 0, *fcW = 0, *fcb = 0;
    const void *ei = 0, *batch = 0;
    int ei_elems = 2 * NEMAX;
    for (int i = 0; i < n_in; i++) {
        int s = in_sizes[i];
        const void* p = d_in[i];
        if (s == NND * DIN)            { x = (const float*)p; }
        else if (s == 2 * NEMAX)       { ei = p; ei_elems = s; }
        else if (s == NND)             { batch = p; }
        else if (s == DIN * DH)        { if (!W1l) W1l = (const float*)p; else W1r = (const float*)p; }
        else if (s == DH * DH)         { if (!W2l) W2l = (const float*)p; else W2r = (const float*)p; }
        else if (s == DH)              { if (!b1)  b1  = (const float*)p; else b2  = (const float*)p; }
        else if (s == DH * NC)         { fcW = (const float*)p; }
        else if (s == NC)              { fcb = (const float*)p; }
    }
    float* out = (float*)d_out;
    int E = ei_elems / 2;
    if (E > NEMAX) E = NEMAX;

    detect_kernel<<<1, 32>>>(ei, batch, E, NND);

    zero_kernel<<<(NND + 255) / 256, 256>>>();
    count_deg_kernel<<<(E + 255) / 256, 256>>>(ei, E);
    scan_local_kernel<<<NCHUNK, 1024>>>();
    scan_chunks_kernel<<<1, 32>>>();
    add_offsets_kernel<<<(NND + 255) / 256, 256>>>();
    fill_csr_kernel<<<(E + 255) / 256, 256>>>(ei, E);

    convert_x_kernel<<<(NND * DIN / 4 + 255) / 256, 256>>>(x);

    dim3 ggrid(DH / 128, (NND + 127) / 128);

    // layer 1
    convert_w_kernel<<<(DIN * DH + 255) / 256, 256>>>(W1l, W1r, DIN);
    agg_mean_kernel<1><<<(NND + 7) / 8, 256>>>(x);
    gemm_wmma_kernel<1><<<ggrid, 256>>>(b1);

    // layer 2
    convert_w_kernel<<<(DH * DH + 255) / 256, 256>>>(W2l, W2r, DH);
    agg_mean_kernel<2><<<(NND + 7) / 8, 256>>>(x);
    gemm_wmma_kernel<2><<<ggrid, 256>>>(b2);

    pool_kernel<<<(NND + 511) / 512, 256>>>(batch);
    final_kernel<<<1, 1024>>>(fcW, fcb, out);
}

// round 12
// speedup vs baseline: 1.2886x; 1.0177x over previous
#include <cuda_runtime.h>
#include <cuda_bf16.h>
#include <mma.h>

using namespace nvcuda;

#define NND    100000
#define NEMAX  1600000
#define DIN    128
#define DH     256
#define NG     64
#define NC     16
#define NCHUNK 98   // ceil(100000/1024)

// ------------------------- scratch (device globals; no allocs) -------------
// NEVER passed as host-side kernel args. Accessed by name inside device code.
__device__ __align__(16) float g_h1[(size_t)NND * DH];
__device__ __align__(16) float g_h2[(size_t)NND * DH];
__device__ __align__(16) __nv_bfloat16 g_mhi[(size_t)NND * DH];
__device__ __align__(16) __nv_bfloat16 g_mlo[(size_t)NND * DH];
__device__ __align__(16) __nv_bfloat16 g_xhi[(size_t)NND * DIN];
__device__ __align__(16) __nv_bfloat16 g_xlo[(size_t)NND * DIN];
__device__ __align__(16) __nv_bfloat16 g_h1hi[(size_t)NND * DH];
__device__ __align__(16) __nv_bfloat16 g_h1lo[(size_t)NND * DH];
__device__ __align__(16) __nv_bfloat16 g_w1lhi[DIN * DH];
__device__ __align__(16) __nv_bfloat16 g_w1llo[DIN * DH];
__device__ __align__(16) __nv_bfloat16 g_w1rhi[DIN * DH];
__device__ __align__(16) __nv_bfloat16 g_w1rlo[DIN * DH];
__device__ __align__(16) __nv_bfloat16 g_w2lhi[DH * DH];
__device__ __align__(16) __nv_bfloat16 g_w2llo[DH * DH];
__device__ __align__(16) __nv_bfloat16 g_w2rhi[DH * DH];
__device__ __align__(16) __nv_bfloat16 g_w2rlo[DH * DH];
__device__ int   g_deg[NND];
__device__ int   g_rowstart[NND + 1];
__device__ int   g_cursor[NND];
__device__ int   g_srcs[NEMAX];
__device__ int   g_chunksum[NCHUNK + 1];
__device__ float g_pool[NG * DH];
__device__ int   g_cnt[NG];
__device__ int   g_ei64;
__device__ int   g_b64;

// --------------------------- helpers ---------------------------------------
__device__ __forceinline__ void split_bf16(float v, __nv_bfloat16& hi, __nv_bfloat16& lo) {
    hi = __float2bfloat16(v);
    lo = __float2bfloat16(v - __bfloat162float(hi));
}
__device__ __forceinline__ unsigned pack2(__nv_bfloat16 a, __nv_bfloat16 b) {
    __nv_bfloat162 t; t.x = a; t.y = b;
    return *(unsigned*)&t;
}
__device__ __forceinline__ int idx_at(const void* p, long long i, int is64) {
    return is64 ? (int)((const long long*)p)[i] : ((const int*)p)[i];
}
__device__ __forceinline__ int clampi(int v, int lo, int hi) {
    return v < lo ? lo : (v > hi ? hi : v);
}

// --------------------------- decisive dtype probe ---------------------------
__global__ void detect_kernel(const void* __restrict__ ei,
                              const void* __restrict__ batch, int E, int NB) {
    if (threadIdx.x != 0 || blockIdx.x != 0) return;
    const long long* el = (const long long*)ei;
    const long long* bl = (const long long*)batch;
    int e64 = 1;
    for (int k = 0; k < 64; k++) {
        long long j = (long long)k * (E - 1) / 63;
        long long v = el[j];
        if (v < 0 || v >= NND) { e64 = 0; break; }
    }
    int b64 = 1;
    long long prev = -1;
    for (int k = 0; k < 64; k++) {
        long long j = (long long)k * (NB / 2 - 1) / 63;
        long long v = bl[j];
        if (v < 0 || v >= NG || v < prev) { b64 = 0; break; }
        prev = v;
    }
    g_ei64 = e64;
    g_b64  = b64;
}

// ------------------------------ setup kernels ------------------------------
__global__ void zero_kernel() {
    int i = blockIdx.x * blockDim.x + threadIdx.x;
    if (i < NND)     g_deg[i] = 0;
    if (i < NG * DH) g_pool[i] = 0.f;
    if (i < NG)      g_cnt[i] = 0;
}

__global__ void count_deg_kernel(const void* __restrict__ ei, int E) {
    int e = blockIdx.x * blockDim.x + threadIdx.x;
    if (e >= E) return;
    int d = clampi(idx_at(ei, (long long)E + e, g_ei64), 0, NND - 1);
    atomicAdd(&g_deg[d], 1);
}

__global__ void scan_local_kernel() {
    __shared__ int s[1024];
    int b = blockIdx.x, tid = threadIdx.x;
    int i = b * 1024 + tid;
    int v = (i < NND) ? g_deg[i] : 0;
    s[tid] = v;
    for (int off = 1; off < 1024; off <<= 1) {
        __syncthreads();
        int t = (tid >= off) ? s[tid - off] : 0;
        __syncthreads();
        s[tid] += t;
    }
    __syncthreads();
    if (i < NND) g_rowstart[i] = s[tid] - v;
    if (tid == 1023) g_chunksum[b] = s[1023];
}

__global__ void scan_chunks_kernel() {
    if (threadIdx.x == 0 && blockIdx.x == 0) {
        int run = 0;
        for (int b = 0; b < NCHUNK; b++) {
            int t = g_chunksum[b];
            g_chunksum[b] = run;
            run += t;
        }
        g_rowstart[NND] = run;
    }
}

__global__ void add_offsets_kernel() {
    int i = blockIdx.x * blockDim.x + threadIdx.x;
    if (i < NND) {
        int v = g_rowstart[i] + g_chunksum[i >> 10];
        g_rowstart[i] = v;
        g_cursor[i]   = v;
    }
}

__global__ void fill_csr_kernel(const void* __restrict__ ei, int E) {
    int e = blockIdx.x * blockDim.x + threadIdx.x;
    if (e >= E) return;
    int is64 = g_ei64;
    int d = clampi(idx_at(ei, (long long)E + e, is64), 0, NND - 1);
    int s = clampi(idx_at(ei, (long long)e, is64), 0, NND - 1);
    int pos = atomicAdd(&g_cursor[d], 1);
    if ((unsigned)pos < NEMAX) g_srcs[pos] = s;
}

// ----------------------- input / weight conversion -------------------------
__global__ void convert_x_kernel(const float* __restrict__ X) {
    int i = blockIdx.x * blockDim.x + threadIdx.x;   // one float4 per thread
    if (i >= NND * DIN / 4) return;
    float4 v = ((const float4*)X)[i];
    __nv_bfloat16 h0, h1, h2, h3, l0, l1, l2, l3;
    split_bf16(v.x, h0, l0); split_bf16(v.y, h1, l1);
    split_bf16(v.z, h2, l2); split_bf16(v.w, h3, l3);
    uint2 uh; uh.x = pack2(h0, h1); uh.y = pack2(h2, h3);
    uint2 ul; ul.x = pack2(l0, l1); ul.y = pack2(l2, l3);
    ((uint2*)g_xhi)[i] = uh;
    ((uint2*)g_xlo)[i] = ul;
}

template <int LAYER>
__global__ void convert_w_kernel(const float* __restrict__ Bl,
                                 const float* __restrict__ Br) {
    constexpr int K = (LAYER == 1) ? DIN : DH;
    __nv_bfloat16* wlhi = (LAYER == 1) ? g_w1lhi : g_w2lhi;
    __nv_bfloat16* wllo = (LAYER == 1) ? g_w1llo : g_w2llo;
    __nv_bfloat16* wrhi = (LAYER == 1) ? g_w1rhi : g_w2rhi;
    __nv_bfloat16* wrlo = (LAYER == 1) ? g_w1rlo : g_w2rlo;
    int i = blockIdx.x * blockDim.x + threadIdx.x;
    if (i >= K * DH) return;
    __nv_bfloat16 hi, lo;
    split_bf16(Bl[i], hi, lo);
    wlhi[i] = hi; wllo[i] = lo;
    split_bf16(Br[i], hi, lo);
    wrhi[i] = hi; wrlo[i] = lo;
}

// --------------------- gather-based mean aggregation -----------------------
// Writes split bf16 means to g_mhi/g_mlo. One warp per destination node.
template <int LAYER>
__global__ void __launch_bounds__(256) agg_mean_kernel(const float* __restrict__ Xarg) {
    constexpr int D = (LAYER == 1) ? DIN : DH;
    const float* __restrict__ X = (LAYER == 1) ? Xarg : (const float*)g_h1;
    int warp = threadIdx.x >> 5;
    int lane = threadIdx.x & 31;
    int node = blockIdx.x * 8 + warp;
    if (node >= NND) return;
    int beg = g_rowstart[node];
    int end = g_rowstart[node + 1];
    float4 a0 = make_float4(0.f, 0.f, 0.f, 0.f);
    float4 a1 = make_float4(0.f, 0.f, 0.f, 0.f);
    for (int e = beg; e < end; e++) {
        int s = g_srcs[e];
        const float4* r = (const float4*)(X + (size_t)s * D) + lane;
        float4 v = r[0];
        a0.x += v.x; a0.y += v.y; a0.z += v.z; a0.w += v.w;
        if (D == 256) {
            float4 w = r[32];
            a1.x += w.x; a1.y += w.y; a1.z += w.z; a1.w += w.w;
        }
    }
    float sc = 1.f / fmaxf((float)(end - beg), 1.f);
    {
        __nv_bfloat16 h0, h1, h2, h3, l0, l1, l2, l3;
        split_bf16(a0.x * sc, h0, l0); split_bf16(a0.y * sc, h1, l1);
        split_bf16(a0.z * sc, h2, l2); split_bf16(a0.w * sc, h3, l3);
        uint2 uh; uh.x = pack2(h0, h1); uh.y = pack2(h2, h3);
        uint2 ul; ul.x = pack2(l0, l1); ul.y = pack2(l2, l3);
        *(uint2*)(g_mhi + (size_t)node * D + lane * 4) = uh;
        *(uint2*)(g_mlo + (size_t)node * D + lane * 4) = ul;
    }
    if (D == 256) {
        __nv_bfloat16 h0, h1, h2, h3, l0, l1, l2, l3;
        split_bf16(a1.x * sc, h0, l0); split_bf16(a1.y * sc, h1, l1);
        split_bf16(a1.z * sc, h2, l2); split_bf16(a1.w * sc, h3, l3);
        uint2 uh; uh.x = pack2(h0, h1); uh.y = pack2(h2, h3);
        uint2 ul; ul.x = pack2(l0, l1); ul.y = pack2(l2, l3);
        *(uint2*)(g_mhi + (size_t)node * D + 128 + lane * 4) = uh;
        *(uint2*)(g_mlo + (size_t)node * D + 128 + lane * 4) = ul;
    }
}

// ----------- dual GEMM + bias + relu via bf16-split tensor cores -----------
// C = relu(mean@Bl + X@Br + bias).  Two halves (l, r); per k-chunk we stage
// Ahi/Alo/Bhi/Blo together and issue all 3 split products (hi*hi, hi*lo,
// lo*hi) while resident: 48 warp-MMAs between barrier pairs.
// Block: 128x128 output, 8 warps (2x4), warp tile 64x32 (4x2 wmma frags).
#define LDA 40
#define LDB 136
template <int LAYER>
__global__ void __launch_bounds__(256) gemm_wmma_kernel(const float* __restrict__ bias) {
    constexpr int K = (LAYER == 1) ? DIN : DH;
    const __nv_bfloat16* AhiH[2] = { g_mhi, (LAYER == 1) ? g_xhi : g_h1hi };
    const __nv_bfloat16* AloH[2] = { g_mlo, (LAYER == 1) ? g_xlo : g_h1lo };
    const __nv_bfloat16* BhiH[2] = { (LAYER == 1) ? g_w1lhi : g_w2lhi,
                                     (LAYER == 1) ? g_w1rhi : g_w2rhi };
    const __nv_bfloat16* BloH[2] = { (LAYER == 1) ? g_w1llo : g_w2llo,
                                     (LAYER == 1) ? g_w1rlo : g_w2rlo };

    __shared__ __nv_bfloat16 Ash[128 * LDA];
    __shared__ __nv_bfloat16 Asl[128 * LDA];
    __shared__ __nv_bfloat16 Bsh[32 * LDB];
    __shared__ __nv_bfloat16 Bsl[32 * LDB];
    __shared__ float Epi[8 * 256];

    int tid = threadIdx.x;
    int wid = tid >> 5, lane = tid & 31;
    int warpRow = wid >> 2, warpCol = wid & 3;
    int rowBase = blockIdx.y * 128;
    int colBase = blockIdx.x * 128;

    wmma::fragment<wmma::accumulator, 16, 16, 16, float> acc[4][2];
    #pragma unroll
    for (int i = 0; i < 4; i++)
        #pragma unroll
        for (int j = 0; j < 2; j++) wmma::fill_fragment(acc[i][j], 0.f);

    int arow = tid >> 1, ahalf = (tid & 1) * 16;   // A: 128 rows x 32 cols
    int brow = tid >> 3, bseg = (tid & 7) * 16;    // B: 32 rows x 128 cols

    for (int h = 0; h < 2; h++) {
        const __nv_bfloat16* Ahi = AhiH[h];
        const __nv_bfloat16* Alo = AloH[h];
        const __nv_bfloat16* Bhi = BhiH[h];
        const __nv_bfloat16* Blo = BloH[h];
        for (int k0 = 0; k0 < K; k0 += 32) {
            uint4 z = make_uint4(0, 0, 0, 0);
            uint4 ah0 = z, ah1 = z, al0 = z, al1 = z;
            int gr = rowBase + arow;
            if (gr < NND) {
                const uint4* sh = (const uint4*)(Ahi + (size_t)gr * K + k0 + ahalf);
                ah0 = sh[0]; ah1 = sh[1];
                const uint4* sl = (const uint4*)(Alo + (size_t)gr * K + k0 + ahalf);
                al0 = sl[0]; al1 = sl[1];
            }
            uint4 bh0, bh1, bl0, bl1;
            {
                const uint4* sh = (const uint4*)(Bhi + (size_t)(k0 + brow) * DH + colBase + bseg);
                bh0 = sh[0]; bh1 = sh[1];
                const uint4* sl = (const uint4*)(Blo + (size_t)(k0 + brow) * DH + colBase + bseg);
                bl0 = sl[0]; bl1 = sl[1];
            }
            __syncthreads();
            {
                uint4* d = (uint4*)(Ash + arow * LDA + ahalf);
                d[0] = ah0; d[1] = ah1;
                uint4* dl = (uint4*)(Asl + arow * LDA + ahalf);
                dl[0] = al0; dl[1] = al1;
                uint4* bh = (uint4*)(Bsh + brow * LDB + bseg);
                bh[0] = bh0; bh[1] = bh1;
                uint4* bl = (uint4*)(Bsl + brow * LDB + bseg);
                bl[0] = bl0; bl[1] = bl1;
            }
            __syncthreads();
            #pragma unroll
            for (int kf = 0; kf < 2; kf++) {
                wmma::fragment<wmma::matrix_a, 16, 16, 16, __nv_bfloat16, wmma::row_major> afh[4], afl[4];
                #pragma unroll
                for (int i = 0; i < 4; i++) {
                    wmma::load_matrix_sync(afh[i], Ash + (warpRow * 64 + i * 16) * LDA + kf * 16, LDA);
                    wmma::load_matrix_sync(afl[i], Asl + (warpRow * 64 + i * 16) * LDA + kf * 16, LDA);
                }
                wmma::fragment<wmma::matrix_b, 16, 16, 16, __nv_bfloat16, wmma::row_major> bfh[2], bfl[2];
                #pragma unroll
                for (int j = 0; j < 2; j++) {
                    wmma::load_matrix_sync(bfh[j], Bsh + (kf * 16) * LDB + warpCol * 32 + j * 16, LDB);
                    wmma::load_matrix_sync(bfl[j], Bsl + (kf * 16) * LDB + warpCol * 32 + j * 16, LDB);
                }
                #pragma unroll
                for (int i = 0; i < 4; i++)
                    #pragma unroll
                    for (int j = 0; j < 2; j++) {
                        wmma::mma_sync(acc[i][j], afh[i], bfh[j], acc[i][j]);
                        wmma::mma_sync(acc[i][j], afh[i], bfl[j], acc[i][j]);
                        wmma::mma_sync(acc[i][j], afl[i], bfh[j], acc[i][j]);
                    }
            }
        }
        __syncthreads();
    }

    // epilogue: one 16x16 fragment at a time through per-warp smem staging
    float* buf = Epi + wid * 256;
    #pragma unroll
    for (int i = 0; i < 4; i++) {
        #pragma unroll
        for (int j = 0; j < 2; j++) {
            wmma::store_matrix_sync(buf, acc[i][j], 16, wmma::mem_row_major);
            __syncwarp();
            #pragma unroll
            for (int e = 0; e < 8; e++) {
                int idx = e * 32 + lane;
                int r = idx >> 4, c = idx & 15;
                int gr = rowBase + warpRow * 64 + i * 16 + r;
                int gc = colBase + warpCol * 32 + j * 16 + c;
                if (gr < NND) {
                    float v = buf[r * 16 + c] + bias[gc];
                    v = v > 0.f ? v : 0.f;
                    if (LAYER == 1) {
                        g_h1[(size_t)gr * DH + gc] = v;
                        __nv_bfloat16 hi, lo;
                        split_bf16(v, hi, lo);
                        g_h1hi[(size_t)gr * DH + gc] = hi;
                        g_h1lo[(size_t)gr * DH + gc] = lo;
                    } else {
                        g_h2[(size_t)gr * DH + gc] = v;
                    }
                }
            }
            __syncwarp();
        }
    }
}

// ----------------------- global mean pool (batch sorted) -------------------
__global__ void __launch_bounds__(256) pool_kernel(const void* __restrict__ batch) {
    __shared__ int sbatch[512];
    int base = blockIdx.x * 512;
    int c = threadIdx.x;
    int is64 = g_b64;
    for (int j = threadIdx.x; j < 512; j += 256) {
        int idx = base + j;
        int g = -1;
        if (idx < NND) g = clampi(idx_at(batch, idx, is64), 0, NG - 1);
        sbatch[j] = g;
    }
    __syncthreads();
    float acc = 0.f;
    int cntl = 0;
    int cur = sbatch[0];
    for (int j = 0; j < 512; j++) {
        int g = sbatch[j];
        if (g != cur) {
            if (cur >= 0) {
                atomicAdd(&g_pool[cur * DH + c], acc);
                if (c == 0) atomicAdd(&g_cnt[cur], cntl);
            }
            acc = 0.f; cntl = 0; cur = g;
        }
        if (g < 0) break;
        acc += g_h2[(size_t)(base + j) * DH + c];
        cntl++;
    }
    if (cur >= 0) {
        atomicAdd(&g_pool[cur * DH + c], acc);
        if (c == 0) atomicAdd(&g_cnt[cur], cntl);
    }
}

__global__ void final_kernel(const float* __restrict__ fcW,
                             const float* __restrict__ fcb,
                             float* __restrict__ out) {
    int t = threadIdx.x;
    int g = t >> 4;
    int cls = t & 15;
    float invc = 1.f / fmaxf((float)g_cnt[g], 1.f);
    float sum = fcb[cls];
    for (int k = 0; k < DH; k++)
        sum += g_pool[g * DH + k] * invc * fcW[k * NC + cls];
    out[g * NC + cls] = sum;
}

// -------------------------------- launch -----------------------------------
extern "C" void kernel_launch(void* const* d_in, const int* in_sizes, int n_in,
                              void* d_out, int out_size) {
    const float *x = 0, *W1l = 0, *b1 = 0, *W1r = 0, *W2l = 0, *b2 = 0,
                *W2r = 0, *fcW = 0, *fcb = 0;
    const void *ei = 0, *batch = 0;
    int ei_elems = 2 * NEMAX;
    for (int i = 0; i < n_in; i++) {
        int s = in_sizes[i];
        const void* p = d_in[i];
        if (s == NND * DIN)            { x = (const float*)p; }
        else if (s == 2 * NEMAX)       { ei = p; ei_elems = s; }
        else if (s == NND)             { batch = p; }
        else if (s == DIN * DH)        { if (!W1l) W1l = (const float*)p; else W1r = (const float*)p; }
        else if (s == DH * DH)         { if (!W2l) W2l = (const float*)p; else W2r = (const float*)p; }
        else if (s == DH)              { if (!b1)  b1  = (const float*)p; else b2  = (const float*)p; }
        else if (s == DH * NC)         { fcW = (const float*)p; }
        else if (s == NC)              { fcb = (const float*)p; }
    }
    float* out = (float*)d_out;
    int E = ei_elems / 2;
    if (E > NEMAX) E = NEMAX;

    detect_kernel<<<1, 32>>>(ei, batch, E, NND);

    zero_kernel<<<(NND + 255) / 256, 256>>>();
    count_deg_kernel<<<(E + 255) / 256, 256>>>(ei, E);
    scan_local_kernel<<<NCHUNK, 1024>>>();
    scan_chunks_kernel<<<1, 32>>>();
    add_offsets_kernel<<<(NND + 255) / 256, 256>>>();
    fill_csr_kernel<<<(E + 255) / 256, 256>>>(ei, E);

    convert_x_kernel<<<(NND * DIN / 4 + 255) / 256, 256>>>(x);
    convert_w_kernel<1><<<(DIN * DH + 255) / 256, 256>>>(W1l, W1r);
    convert_w_kernel<2><<<(DH * DH + 255) / 256, 256>>>(W2l, W2r);

    dim3 ggrid(DH / 128, (NND + 127) / 128);

    // layer 1
    agg_mean_kernel<1><<<(NND + 7) / 8, 256>>>(x);
    gemm_wmma_kernel<1><<<ggrid, 256>>>(b1);

    // layer 2
    agg_mean_kernel<2><<<(NND + 7) / 8, 256>>>(x);
    gemm_wmma_kernel<2><<<ggrid, 256>>>(b2);

    pool_kernel<<<(NND + 511) / 512, 256>>>(batch);
    final_kernel<<<1, 1024>>>(fcW, fcb, out);
}

// round 16
// speedup vs baseline: 1.4621x; 1.1346x over previous
#include <cuda_runtime.h>
#include <cuda_bf16.h>
#include <mma.h>

using namespace nvcuda;

#define NND    100000
#define NEMAX  1600000
#define DIN    128
#define DH     256
#define NG     64
#define NC     16
#define NCHUNK 98   // ceil(100000/1024)

// ------------------------- scratch (device globals; no allocs) -------------
// NEVER passed as host-side kernel args. Accessed by name inside device code.
__device__ __align__(16) float g_h2[(size_t)NND * DH];
__device__ __align__(16) __nv_bfloat16 g_mhi[(size_t)NND * DH];
__device__ __align__(16) __nv_bfloat16 g_mlo[(size_t)NND * DH];
__device__ __align__(16) __nv_bfloat16 g_xhi[(size_t)NND * DIN];
__device__ __align__(16) __nv_bfloat16 g_xlo[(size_t)NND * DIN];
__device__ __align__(16) __nv_bfloat16 g_h1hi[(size_t)NND * DH];
__device__ __align__(16) __nv_bfloat16 g_h1lo[(size_t)NND * DH];
// weights split, K x DH row-major (as given)
__device__ __align__(16) __nv_bfloat16 g_w1lhi[DIN * DH];
__device__ __align__(16) __nv_bfloat16 g_w1llo[DIN * DH];
__device__ __align__(16) __nv_bfloat16 g_w1rhi[DIN * DH];
__device__ __align__(16) __nv_bfloat16 g_w1rlo[DIN * DH];
__device__ __align__(16) __nv_bfloat16 g_w2lhi[DH * DH];
__device__ __align__(16) __nv_bfloat16 g_w2llo[DH * DH];
__device__ __align__(16) __nv_bfloat16 g_w2rhi[DH * DH];
__device__ __align__(16) __nv_bfloat16 g_w2rlo[DH * DH];
__device__ int   g_deg[NND];
__device__ int   g_rowstart[NND + 1];
__device__ int   g_cursor[NND];
__device__ int   g_srcs[NEMAX];
__device__ int   g_chunksum[NCHUNK + 1];
__device__ float g_pool[NG * DH];
__device__ int   g_cnt[NG];
__device__ int   g_ei64;
__device__ int   g_b64;

// --------------------------- helpers ---------------------------------------
__device__ __forceinline__ void split_bf16(float v, __nv_bfloat16& hi, __nv_bfloat16& lo) {
    hi = __float2bfloat16(v);
    lo = __float2bfloat16(v - __bfloat162float(hi));
}
__device__ __forceinline__ unsigned pack2(__nv_bfloat16 a, __nv_bfloat16 b) {
    __nv_bfloat162 t; t.x = a; t.y = b;
    return *(unsigned*)&t;
}
__device__ __forceinline__ int idx_at(const void* p, long long i, int is64) {
    return is64 ? (int)((const long long*)p)[i] : ((const int*)p)[i];
}
__device__ __forceinline__ int clampi(int v, int lo, int hi) {
    return v < lo ? lo : (v > hi ? hi : v);
}
__device__ __forceinline__ unsigned smem_u32(const void* p) {
    unsigned a;
    asm("{ .reg .u64 t; cvta.to.shared.u64 t, %1; cvt.u32.u64 %0, t; }" : "=r"(a) : "l"(p));
    return a;
}
__device__ __forceinline__ void cp16(unsigned dst, const void* src) {
    asm volatile("cp.async.cg.shared.global [%0], [%1], 16;" :: "r"(dst), "l"(src));
}
__device__ __forceinline__ void cp_commit() {
    asm volatile("cp.async.commit_group;" ::: "memory");
}
template <int N>
__device__ __forceinline__ void cp_wait() {
    asm volatile("cp.async.wait_group %0;" :: "n"(N) : "memory");
}

// --------------------------- decisive dtype probe ---------------------------
__global__ void detect_kernel(const void* __restrict__ ei,
                              const void* __restrict__ batch, int E, int NB) {
    if (threadIdx.x != 0 || blockIdx.x != 0) return;
    const long long* el = (const long long*)ei;
    const long long* bl = (const long long*)batch;
    int e64 = 1;
    for (int k = 0; k < 64; k++) {
        long long j = (long long)k * (E - 1) / 63;
        long long v = el[j];
        if (v < 0 || v >= NND) { e64 = 0; break; }
    }
    int b64 = 1;
    long long prev = -1;
    for (int k = 0; k < 64; k++) {
        long long j = (long long)k * (NB / 2 - 1) / 63;
        long long v = bl[j];
        if (v < 0 || v >= NG || v < prev) { b64 = 0; break; }
        prev = v;
    }
    g_ei64 = e64;
    g_b64  = b64;
}

// ------------------------------ setup kernels ------------------------------
__global__ void zero_kernel() {
    int i = blockIdx.x * blockDim.x + threadIdx.x;
    if (i < NND)     g_deg[i] = 0;
    if (i < NG * DH) g_pool[i] = 0.f;
    if (i < NG)      g_cnt[i] = 0;
}

__global__ void count_deg_kernel(const void* __restrict__ ei, int E) {
    int e = blockIdx.x * blockDim.x + threadIdx.x;
    if (e >= E) return;
    int d = clampi(idx_at(ei, (long long)E + e, g_ei64), 0, NND - 1);
    atomicAdd(&g_deg[d], 1);
}

__global__ void scan_local_kernel() {
    __shared__ int s[1024];
    int b = blockIdx.x, tid = threadIdx.x;
    int i = b * 1024 + tid;
    int v = (i < NND) ? g_deg[i] : 0;
    s[tid] = v;
    for (int off = 1; off < 1024; off <<= 1) {
        __syncthreads();
        int t = (tid >= off) ? s[tid - off] : 0;
        __syncthreads();
        s[tid] += t;
    }
    __syncthreads();
    if (i < NND) g_rowstart[i] = s[tid] - v;
    if (tid == 1023) g_chunksum[b] = s[1023];
}

__global__ void scan_chunks_kernel() {
    if (threadIdx.x == 0 && blockIdx.x == 0) {
        int run = 0;
        for (int b = 0; b < NCHUNK; b++) {
            int t = g_chunksum[b];
            g_chunksum[b] = run;
            run += t;
        }
        g_rowstart[NND] = run;
    }
}

__global__ void add_offsets_kernel() {
    int i = blockIdx.x * blockDim.x + threadIdx.x;
    if (i < NND) {
        int v = g_rowstart[i] + g_chunksum[i >> 10];
        g_rowstart[i] = v;
        g_cursor[i]   = v;
    }
}

__global__ void fill_csr_kernel(const void* __restrict__ ei, int E) {
    int e = blockIdx.x * blockDim.x + threadIdx.x;
    if (e >= E) return;
    int is64 = g_ei64;
    int d = clampi(idx_at(ei, (long long)E + e, is64), 0, NND - 1);
    int s = clampi(idx_at(ei, (long long)e, is64), 0, NND - 1);
    int pos = atomicAdd(&g_cursor[d], 1);
    if ((unsigned)pos < NEMAX) g_srcs[pos] = s;
}

// ----------------------- input / weight conversion -------------------------
__global__ void convert_x_kernel(const float* __restrict__ X) {
    int i = blockIdx.x * blockDim.x + threadIdx.x;
    if (i >= NND * DIN / 4) return;
    float4 v = ((const float4*)X)[i];
    __nv_bfloat16 h0, h1, h2, h3, l0, l1, l2, l3;
    split_bf16(v.x, h0, l0); split_bf16(v.y, h1, l1);
    split_bf16(v.z, h2, l2); split_bf16(v.w, h3, l3);
    uint2 uh; uh.x = pack2(h0, h1); uh.y = pack2(h2, h3);
    uint2 ul; ul.x = pack2(l0, l1); ul.y = pack2(l2, l3);
    ((uint2*)g_xhi)[i] = uh;
    ((uint2*)g_xlo)[i] = ul;
}

template <int LAYER>
__global__ void convert_w_kernel(const float* __restrict__ Bl,
                                 const float* __restrict__ Br) {
    constexpr int K = (LAYER == 1) ? DIN : DH;
    __nv_bfloat16* wlhi = (LAYER == 1) ? g_w1lhi : g_w2lhi;
    __nv_bfloat16* wllo = (LAYER == 1) ? g_w1llo : g_w2llo;
    __nv_bfloat16* wrhi = (LAYER == 1) ? g_w1rhi : g_w2rhi;
    __nv_bfloat16* wrlo = (LAYER == 1) ? g_w1rlo : g_w2rlo;
    int i = blockIdx.x * blockDim.x + threadIdx.x;
    if (i >= K * DH) return;
    __nv_bfloat16 hi, lo;
    split_bf16(Bl[i], hi, lo);
    wlhi[i] = hi; wllo[i] = lo;
    split_bf16(Br[i], hi, lo);
    wrhi[i] = hi; wrlo[i] = lo;
}

// --------------------- gather-based mean aggregation -----------------------
// 2-edge unrolled for MLP. LAYER 1 reads x (fp32 arg); LAYER 2 reads h1 split.
template <int LAYER>
__global__ void __launch_bounds__(256) agg_mean_kernel(const float* __restrict__ Xarg) {
    constexpr int D = (LAYER == 1) ? DIN : DH;
    int warp = threadIdx.x >> 5;
    int lane = threadIdx.x & 31;
    int node = blockIdx.x * 8 + warp;
    if (node >= NND) return;
    int beg = g_rowstart[node];
    int end = g_rowstart[node + 1];
    float4 a0 = make_float4(0.f, 0.f, 0.f, 0.f);
    float4 a1 = make_float4(0.f, 0.f, 0.f, 0.f);
    int e = beg;
    if (LAYER == 1) {
        const float* __restrict__ X = Xarg;
        for (; e + 1 < end; e += 2) {
            int s0 = g_srcs[e], s1 = g_srcs[e + 1];
            float4 v0 = ((const float4*)(X + (size_t)s0 * D))[lane];
            float4 v1 = ((const float4*)(X + (size_t)s1 * D))[lane];
            a0.x += v0.x; a0.y += v0.y; a0.z += v0.z; a0.w += v0.w;
            a0.x += v1.x; a0.y += v1.y; a0.z += v1.z; a0.w += v1.w;
        }
        if (e < end) {
            float4 v0 = ((const float4*)(X + (size_t)g_srcs[e] * D))[lane];
            a0.x += v0.x; a0.y += v0.y; a0.z += v0.z; a0.w += v0.w;
        }
    } else {
        // reconstruct h1 = hi + lo from split arrays; 8 elems per lane
        for (; e + 1 < end; e += 2) {
            int s0 = g_srcs[e], s1 = g_srcs[e + 1];
            const __nv_bfloat162* h0a = (const __nv_bfloat162*)(g_h1hi + (size_t)s0 * D) + lane * 2;
            const __nv_bfloat162* l0a = (const __nv_bfloat162*)(g_h1lo + (size_t)s0 * D) + lane * 2;
            const __nv_bfloat162* h1a = (const __nv_bfloat162*)(g_h1hi + (size_t)s1 * D) + lane * 2;
            const __nv_bfloat162* l1a = (const __nv_bfloat162*)(g_h1lo + (size_t)s1 * D) + lane * 2;
            float2 p, q;
            p = __bfloat1622float2(h0a[0]);  q = __bfloat1622float2(l0a[0]);
            a0.x += p.x + q.x; a0.y += p.y + q.y;
            p = __bfloat1622float2(h0a[1]);  q = __bfloat1622float2(l0a[1]);
            a0.z += p.x + q.x; a0.w += p.y + q.y;
            p = __bfloat1622float2(h0a[64]); q = __bfloat1622float2(l0a[64]);
            a1.x += p.x + q.x; a1.y += p.y + q.y;
            p = __bfloat1622float2(h0a[65]); q = __bfloat1622float2(l0a[65]);
            a1.z += p.x + q.x; a1.w += p.y + q.y;
            p = __bfloat1622float2(h1a[0]);  q = __bfloat1622float2(l1a[0]);
            a0.x += p.x + q.x; a0.y += p.y + q.y;
            p = __bfloat1622float2(h1a[1]);  q = __bfloat1622float2(l1a[1]);
            a0.z += p.x + q.x; a0.w += p.y + q.y;
            p = __bfloat1622float2(h1a[64]); q = __bfloat1622float2(l1a[64]);
            a1.x += p.x + q.x; a1.y += p.y + q.y;
            p = __bfloat1622float2(h1a[65]); q = __bfloat1622float2(l1a[65]);
            a1.z += p.x + q.x; a1.w += p.y + q.y;
        }
        if (e < end) {
            int s0 = g_srcs[e];
            const __nv_bfloat162* h0a = (const __nv_bfloat162*)(g_h1hi + (size_t)s0 * D) + lane * 2;
            const __nv_bfloat162* l0a = (const __nv_bfloat162*)(g_h1lo + (size_t)s0 * D) + lane * 2;
            float2 p, q;
            p = __bfloat1622float2(h0a[0]);  q = __bfloat1622float2(l0a[0]);
            a0.x += p.x + q.x; a0.y += p.y + q.y;
            p = __bfloat1622float2(h0a[1]);  q = __bfloat1622float2(l0a[1]);
            a0.z += p.x + q.x; a0.w += p.y + q.y;
            p = __bfloat1622float2(h0a[64]); q = __bfloat1622float2(l0a[64]);
            a1.x += p.x + q.x; a1.y += p.y + q.y;
            p = __bfloat1622float2(h0a[65]); q = __bfloat1622float2(l0a[65]);
            a1.z += p.x + q.x; a1.w += p.y + q.y;
        }
    }
    float sc = 1.f / fmaxf((float)(end - beg), 1.f);
    {
        __nv_bfloat16 h0, h1, h2, h3, l0, l1, l2, l3;
        split_bf16(a0.x * sc, h0, l0); split_bf16(a0.y * sc, h1, l1);
        split_bf16(a0.z * sc, h2, l2); split_bf16(a0.w * sc, h3, l3);
        uint2 uh; uh.x = pack2(h0, h1); uh.y = pack2(h2, h3);
        uint2 ul; ul.x = pack2(l0, l1); ul.y = pack2(l2, l3);
        *(uint2*)(g_mhi + (size_t)node * D + lane * 4) = uh;
        *(uint2*)(g_mlo + (size_t)node * D + lane * 4) = ul;
    }
    if (D == 256) {
        __nv_bfloat16 h0, h1, h2, h3, l0, l1, l2, l3;
        split_bf16(a1.x * sc, h0, l0); split_bf16(a1.y * sc, h1, l1);
        split_bf16(a1.z * sc, h2, l2); split_bf16(a1.w * sc, h3, l3);
        uint2 uh; uh.x = pack2(h0, h1); uh.y = pack2(h2, h3);
        uint2 ul; ul.x = pack2(l0, l1); ul.y = pack2(l2, l3);
        *(uint2*)(g_mhi + (size_t)node * D + 128 + lane * 4) = uh;
        *(uint2*)(g_mlo + (size_t)node * D + 128 + lane * 4) = ul;
    }
}

// ----------- dual GEMM + bias + relu, bf16-split wmma, cp.async ------------
// One CTA: full 128x256 output tile. 512 threads = 16 warps (2 x 8),
// warp tile 64x32 (4x2 frags). Double-buffered 32-wide k-chunks over
// sequence (l-half chunks..., r-half chunks...). 3 split products per frag.
#define LDA 40     // bf16 elems per A row (32 + 8 pad)
#define LDB 264    // bf16 elems per B row (256 + 8 pad)
#define OF_AHI 0
#define OF_ALO 10240     // 128*40*2
#define OF_BHI 20480
#define OF_BLO 37376     // +32*264*2
#define BUFSZ  54272
#define GSMEM  (2 * BUFSZ)

template <int LAYER>
__global__ void __launch_bounds__(512) gemm_wmma_kernel(const float* __restrict__ bias) {
    constexpr int K = (LAYER == 1) ? DIN : DH;
    constexpr int CPH = K / 32;            // chunks per half
    const __nv_bfloat16* Ahi2[2] = { g_mhi, (LAYER == 1) ? g_xhi : g_h1hi };
    const __nv_bfloat16* Alo2[2] = { g_mlo, (LAYER == 1) ? g_xlo : g_h1lo };
    const __nv_bfloat16* Bhi2[2] = { (LAYER == 1) ? g_w1lhi : g_w2lhi,
                                     (LAYER == 1) ? g_w1rhi : g_w2rhi };
    const __nv_bfloat16* Blo2[2] = { (LAYER == 1) ? g_w1llo : g_w2llo,
                                     (LAYER == 1) ? g_w1rlo : g_w2rlo };

    extern __shared__ char smem[];
    unsigned sb = smem_u32(smem);
    int tid = threadIdx.x;
    int wid = tid >> 5, lane = tid & 31;
    int warpRow = wid >> 3, warpCol = wid & 7;
    int rowBase = blockIdx.x * 128;

    wmma::fragment<wmma::accumulator, 16, 16, 16, float> acc[4][2];
    #pragma unroll
    for (int i = 0; i < 4; i++)
        #pragma unroll
        for (int j = 0; j < 2; j++) wmma::fill_fragment(acc[i][j], 0.f);

    // staging thread mapping
    int arow = tid >> 2, ac = (tid & 3) * 8;       // A: 512 chunks of 16B
    int brow0 = tid >> 5, bc0 = (tid & 31) * 8;    // B: chunk idx = tid, tid+512
    int brow1 = (tid + 512) >> 5, bc1 = ((tid + 512) & 31) * 8;

    const int total = 2 * CPH;
    auto stage = [&](int s, int buf) {
        int h = s / CPH, k0 = (s % CPH) * 32;
        const __nv_bfloat16* Ah = Ahi2[h];
        const __nv_bfloat16* Al = Alo2[h];
        const __nv_bfloat16* Bh = Bhi2[h];
        const __nv_bfloat16* Bl = Blo2[h];
        unsigned base = sb + buf * BUFSZ;
        int gr = rowBase + arow;
        if (gr > NND - 1) gr = NND - 1;            // content unused for OOB rows
        cp16(base + OF_AHI + arow * (LDA * 2) + ac * 2, Ah + (size_t)gr * K + k0 + ac);
        cp16(base + OF_ALO + arow * (LDA * 2) + ac * 2, Al + (size_t)gr * K + k0 + ac);
        cp16(base + OF_BHI + brow0 * (LDB * 2) + bc0 * 2, Bh + (size_t)(k0 + brow0) * DH + bc0);
        cp16(base + OF_BHI + brow1 * (LDB * 2) + bc1 * 2, Bh + (size_t)(k0 + brow1) * DH + bc1);
        cp16(base + OF_BLO + brow0 * (LDB * 2) + bc0 * 2, Bl + (size_t)(k0 + brow0) * DH + bc0);
        cp16(base + OF_BLO + brow1 * (LDB * 2) + bc1 * 2, Bl + (size_t)(k0 + brow1) * DH + bc1);
        cp_commit();
    };

    stage(0, 0);
    for (int s = 0; s < total; s++) {
        int buf = s & 1;
        if (s + 1 < total) { stage(s + 1, buf ^ 1); cp_wait<1>(); }
        else               { cp_wait<0>(); }
        __syncthreads();
        const __nv_bfloat16* Ash = (const __nv_bfloat16*)(smem + buf * BUFSZ + OF_AHI);
        const __nv_bfloat16* Asl = (const __nv_bfloat16*)(smem + buf * BUFSZ + OF_ALO);
        const __nv_bfloat16* Bsh = (const __nv_bfloat16*)(smem + buf * BUFSZ + OF_BHI);
        const __nv_bfloat16* Bsl = (const __nv_bfloat16*)(smem + buf * BUFSZ + OF_BLO);
        #pragma unroll
        for (int kf = 0; kf < 2; kf++) {
            wmma::fragment<wmma::matrix_b, 16, 16, 16, __nv_bfloat16, wmma::row_major> bfh[2], bfl[2];
            #pragma unroll
            for (int j = 0; j < 2; j++) {
                wmma::load_matrix_sync(bfh[j], Bsh + (kf * 16) * LDB + warpCol * 32 + j * 16, LDB);
                wmma::load_matrix_sync(bfl[j], Bsl + (kf * 16) * LDB + warpCol * 32 + j * 16, LDB);
            }
            #pragma unroll
            for (int i = 0; i < 4; i++) {
                wmma::fragment<wmma::matrix_a, 16, 16, 16, __nv_bfloat16, wmma::row_major> afh, afl;
                wmma::load_matrix_sync(afh, Ash + (warpRow * 64 + i * 16) * LDA + kf * 16, LDA);
                wmma::load_matrix_sync(afl, Asl + (warpRow * 64 + i * 16) * LDA + kf * 16, LDA);
                #pragma unroll
                for (int j = 0; j < 2; j++) {
                    wmma::mma_sync(acc[i][j], afh, bfh[j], acc[i][j]);
                    wmma::mma_sync(acc[i][j], afh, bfl[j], acc[i][j]);
                    wmma::mma_sync(acc[i][j], afl, bfh[j], acc[i][j]);
                }
            }
        }
        __syncthreads();
    }

    // epilogue via per-warp smem staging (aliases buffers; sync'd above)
    float* buf = (float*)(smem) + wid * 256;
    #pragma unroll
    for (int i = 0; i < 4; i++) {
        #pragma unroll
        for (int j = 0; j < 2; j++) {
            wmma::store_matrix_sync(buf, acc[i][j], 16, wmma::mem_row_major);
            __syncwarp();
            #pragma unroll
            for (int e = 0; e < 8; e++) {
                int idx = e * 32 + lane;
                int r = idx >> 4, c = idx & 15;
                int gr = rowBase + warpRow * 64 + i * 16 + r;
                int gc = warpCol * 32 + j * 16 + c;
                if (gr < NND) {
                    float v = buf[r * 16 + c] + bias[gc];
                    v = v > 0.f ? v : 0.f;
                    if (LAYER == 1) {
                        __nv_bfloat16 hi, lo;
                        split_bf16(v, hi, lo);
                        g_h1hi[(size_t)gr * DH + gc] = hi;
                        g_h1lo[(size_t)gr * DH + gc] = lo;
                    } else {
                        g_h2[(size_t)gr * DH + gc] = v;
                    }
                }
            }
            __syncwarp();
        }
    }
}

// ----------------------- global mean pool (batch sorted) -------------------
__global__ void __launch_bounds__(256) pool_kernel(const void* __restrict__ batch) {
    __shared__ int sbatch[512];
    int base = blockIdx.x * 512;
    int c = threadIdx.x;
    int is64 = g_b64;
    for (int j = threadIdx.x; j < 512; j += 256) {
        int idx = base + j;
        int g = -1;
        if (idx < NND) g = clampi(idx_at(batch, idx, is64), 0, NG - 1);
        sbatch[j] = g;
    }
    __syncthreads();
    float acc = 0.f;
    int cntl = 0;
    int cur = sbatch[0];
    for (int j = 0; j < 512; j++) {
        int g = sbatch[j];
        if (g != cur) {
            if (cur >= 0) {
                atomicAdd(&g_pool[cur * DH + c], acc);
                if (c == 0) atomicAdd(&g_cnt[cur], cntl);
            }
            acc = 0.f; cntl = 0; cur = g;
        }
        if (g < 0) break;
        acc += g_h2[(size_t)(base + j) * DH + c];
        cntl++;
    }
    if (cur >= 0) {
        atomicAdd(&g_pool[cur * DH + c], acc);
        if (c == 0) atomicAdd(&g_cnt[cur], cntl);
    }
}

__global__ void final_kernel(const float* __restrict__ fcW,
                             const float* __restrict__ fcb,
                             float* __restrict__ out) {
    int t = threadIdx.x;
    int g = t >> 4;
    int cls = t & 15;
    float invc = 1.f / fmaxf((float)g_cnt[g], 1.f);
    float sum = fcb[cls];
    for (int k = 0; k < DH; k++)
        sum += g_pool[g * DH + k] * invc * fcW[k * NC + cls];
    out[g * NC + cls] = sum;
}

// -------------------------------- launch -----------------------------------
extern "C" void kernel_launch(void* const* d_in, const int* in_sizes, int n_in,
                              void* d_out, int out_size) {
    const float *x = 0, *W1l = 0, *b1 = 0, *W1r = 0, *W2l = 0, *b2 = 0,
                *W2r = 0, *fcW = 0, *fcb = 0;
    const void *ei = 0, *batch = 0;
    int ei_elems = 2 * NEMAX;
    for (int i = 0; i < n_in; i++) {
        int s = in_sizes[i];
        const void* p = d_in[i];
        if (s == NND * DIN)            { x = (const float*)p; }
        else if (s == 2 * NEMAX)       { ei = p; ei_elems = s; }
        else if (s == NND)             { batch = p; }
        else if (s == DIN * DH)        { if (!W1l) W1l = (const float*)p; else W1r = (const float*)p; }
        else if (s == DH * DH)         { if (!W2l) W2l = (const float*)p; else W2r = (const float*)p; }
        else if (s == DH)              { if (!b1)  b1  = (const float*)p; else b2  = (const float*)p; }
        else if (s == DH * NC)         { fcW = (const float*)p; }
        else if (s == NC)              { fcb = (const float*)p; }
    }
    float* out = (float*)d_out;
    int E = ei_elems / 2;
    if (E > NEMAX) E = NEMAX;

    cudaFuncSetAttribute(gemm_wmma_kernel<1>, cudaFuncAttributeMaxDynamicSharedMemorySize, GSMEM);
    cudaFuncSetAttribute(gemm_wmma_kernel<2>, cudaFuncAttributeMaxDynamicSharedMemorySize, GSMEM);

    detect_kernel<<<1, 32>>>(ei, batch, E, NND);

    zero_kernel<<<(NND + 255) / 256, 256>>>();
    count_deg_kernel<<<(E + 255) / 256, 256>>>(ei, E);
    scan_local_kernel<<<NCHUNK, 1024>>>();
    scan_chunks_kernel<<<1, 32>>>();
    add_offsets_kernel<<<(NND + 255) / 256, 256>>>();
    fill_csr_kernel<<<(E + 255) / 256, 256>>>(ei, E);

    convert_x_kernel<<<(NND * DIN / 4 + 255) / 256, 256>>>(x);
    convert_w_kernel<1><<<(DIN * DH + 255) / 256, 256>>>(W1l, W1r);
    convert_w_kernel<2><<<(DH * DH + 255) / 256, 256>>>(W2l, W2r);

    int ggrid = (NND + 127) / 128;   // 782

    // layer 1
    agg_mean_kernel<1><<<(NND + 7) / 8, 256>>>(x);
    gemm_wmma_kernel<1><<<ggrid, 512, GSMEM>>>(b1);

    // layer 2
    agg_mean_kernel<2><<<(NND + 7) / 8, 256>>>(x);
    gemm_wmma_kernel<2><<<ggrid, 512, GSMEM>>>(b2);

    pool_kernel<<<(NND + 511) / 512, 256>>>(batch);
    final_kernel<<<1, 1024>>>(fcW, fcb, out);
}

// round 17
// speedup vs baseline: 2.0683x; 1.4146x over previous
#include <cuda_runtime.h>
#include <cuda_fp16.h>
#include <mma.h>

using namespace nvcuda;

#define NND    100000
#define NEMAX  1600000
#define DIN    128
#define DH     256
#define NG     64
#define NC     16
#define NCHUNK 98   // ceil(100000/1024)

// ------------------------- scratch (device globals; no allocs) -------------
// NEVER passed as host-side kernel args. Accessed by name inside device code.
__device__ __align__(16) float  g_h2[(size_t)NND * DH];
__device__ __align__(16) __half g_mhi[(size_t)NND * DH];   // mean split hi
__device__ __align__(16) __half g_mlo[(size_t)NND * DH];   // mean split lo
__device__ __align__(16) __half g_xhi[(size_t)NND * DIN];
__device__ __align__(16) __half g_xlo[(size_t)NND * DIN];
__device__ __align__(16) __half g_h1[(size_t)NND * DH];    // h1 single fp16
// weights single fp16, K x DH row-major
__device__ __align__(16) __half g_w1l[DIN * DH];
__device__ __align__(16) __half g_w1r[DIN * DH];
__device__ __align__(16) __half g_w2l[DH * DH];
__device__ __align__(16) __half g_w2r[DH * DH];
__device__ int   g_deg[NND];
__device__ int   g_rowstart[NND + 1];
__device__ int   g_cursor[NND];
__device__ int   g_srcs[NEMAX];
__device__ int   g_chunksum[NCHUNK + 1];
__device__ float g_pool[NG * DH];
__device__ int   g_cnt[NG];
__device__ int   g_ei64;
__device__ int   g_b64;

// --------------------------- helpers ---------------------------------------
__device__ __forceinline__ void split_f16(float v, __half& hi, __half& lo) {
    hi = __float2half_rn(v);
    lo = __float2half_rn(v - __half2float(hi));
}
__device__ __forceinline__ int idx_at(const void* p, long long i, int is64) {
    return is64 ? (int)((const long long*)p)[i] : ((const int*)p)[i];
}
__device__ __forceinline__ int clampi(int v, int lo, int hi) {
    return v < lo ? lo : (v > hi ? hi : v);
}
__device__ __forceinline__ unsigned smem_u32(const void* p) {
    unsigned a;
    asm("{ .reg .u64 t; cvta.to.shared.u64 t, %1; cvt.u32.u64 %0, t; }" : "=r"(a) : "l"(p));
    return a;
}
__device__ __forceinline__ void cp16(unsigned dst, const void* src) {
    asm volatile("cp.async.cg.shared.global [%0], [%1], 16;" :: "r"(dst), "l"(src));
}
__device__ __forceinline__ void cp_commit() {
    asm volatile("cp.async.commit_group;" ::: "memory");
}
template <int N>
__device__ __forceinline__ void cp_wait() {
    asm volatile("cp.async.wait_group %0;" :: "n"(N) : "memory");
}

// --------------------------- decisive dtype probe ---------------------------
__global__ void detect_kernel(const void* __restrict__ ei,
                              const void* __restrict__ batch, int E, int NB) {
    if (threadIdx.x != 0 || blockIdx.x != 0) return;
    const long long* el = (const long long*)ei;
    const long long* bl = (const long long*)batch;
    int e64 = 1;
    for (int k = 0; k < 64; k++) {
        long long j = (long long)k * (E - 1) / 63;
        long long v = el[j];
        if (v < 0 || v >= NND) { e64 = 0; break; }
    }
    int b64 = 1;
    long long prev = -1;
    for (int k = 0; k < 64; k++) {
        long long j = (long long)k * (NB / 2 - 1) / 63;
        long long v = bl[j];
        if (v < 0 || v >= NG || v < prev) { b64 = 0; break; }
        prev = v;
    }
    g_ei64 = e64;
    g_b64  = b64;
}

// ------------------------------ setup kernels ------------------------------
__global__ void zero_kernel() {
    int i = blockIdx.x * blockDim.x + threadIdx.x;
    if (i < NND)     g_deg[i] = 0;
    if (i < NG * DH) g_pool[i] = 0.f;
    if (i < NG)      g_cnt[i] = 0;
}

__global__ void count_deg_kernel(const void* __restrict__ ei, int E) {
    int e = blockIdx.x * blockDim.x + threadIdx.x;
    if (e >= E) return;
    int d = clampi(idx_at(ei, (long long)E + e, g_ei64), 0, NND - 1);
    atomicAdd(&g_deg[d], 1);
}

__global__ void scan_local_kernel() {
    __shared__ int s[1024];
    int b = blockIdx.x, tid = threadIdx.x;
    int i = b * 1024 + tid;
    int v = (i < NND) ? g_deg[i] : 0;
    s[tid] = v;
    for (int off = 1; off < 1024; off <<= 1) {
        __syncthreads();
        int t = (tid >= off) ? s[tid - off] : 0;
        __syncthreads();
        s[tid] += t;
    }
    __syncthreads();
    if (i < NND) g_rowstart[i] = s[tid] - v;
    if (tid == 1023) g_chunksum[b] = s[1023];
}

__global__ void scan_chunks_kernel() {
    if (threadIdx.x == 0 && blockIdx.x == 0) {
        int run = 0;
        for (int b = 0; b < NCHUNK; b++) {
            int t = g_chunksum[b];
            g_chunksum[b] = run;
            run += t;
        }
        g_rowstart[NND] = run;
    }
}

__global__ void add_offsets_kernel() {
    int i = blockIdx.x * blockDim.x + threadIdx.x;
    if (i < NND) {
        int v = g_rowstart[i] + g_chunksum[i >> 10];
        g_rowstart[i] = v;
        g_cursor[i]   = v;
    }
}

__global__ void fill_csr_kernel(const void* __restrict__ ei, int E) {
    int e = blockIdx.x * blockDim.x + threadIdx.x;
    if (e >= E) return;
    int is64 = g_ei64;
    int d = clampi(idx_at(ei, (long long)E + e, is64), 0, NND - 1);
    int s = clampi(idx_at(ei, (long long)e, is64), 0, NND - 1);
    int pos = atomicAdd(&g_cursor[d], 1);
    if ((unsigned)pos < NEMAX) g_srcs[pos] = s;
}

// ----------------------- input / weight conversion -------------------------
__global__ void convert_x_kernel(const float* __restrict__ X) {
    int i = blockIdx.x * blockDim.x + threadIdx.x;   // one float4 per thread
    if (i >= NND * DIN / 4) return;
    float4 v = ((const float4*)X)[i];
    __half h0, h1, h2, h3, l0, l1, l2, l3;
    split_f16(v.x, h0, l0); split_f16(v.y, h1, l1);
    split_f16(v.z, h2, l2); split_f16(v.w, h3, l3);
    __half2 hh[2] = { __halves2half2(h0, h1), __halves2half2(h2, h3) };
    __half2 ll[2] = { __halves2half2(l0, l1), __halves2half2(l2, l3) };
    ((uint2*)g_xhi)[i] = *(uint2*)hh;
    ((uint2*)g_xlo)[i] = *(uint2*)ll;
}

template <int LAYER>
__global__ void convert_w_kernel(const float* __restrict__ Bl,
                                 const float* __restrict__ Br) {
    constexpr int K = (LAYER == 1) ? DIN : DH;
    __half* wl = (LAYER == 1) ? g_w1l : g_w2l;
    __half* wr = (LAYER == 1) ? g_w1r : g_w2r;
    int i = blockIdx.x * blockDim.x + threadIdx.x;
    if (i >= K * DH) return;
    wl[i] = __float2half_rn(Bl[i]);
    wr[i] = __float2half_rn(Br[i]);
}

// --------------------- gather-based mean aggregation -----------------------
// LAYER 1: reads x fp32 (arg), D=128, cols lane*4..+3.
// LAYER 2: reads h1 single fp16, D=256, cols lane*8..+7 (one uint4/edge/lane).
// Writes split fp16 means. 2-edge unroll for MLP.
template <int LAYER>
__global__ void __launch_bounds__(256) agg_mean_kernel(const float* __restrict__ Xarg) {
    constexpr int D = (LAYER == 1) ? DIN : DH;
    int warp = threadIdx.x >> 5;
    int lane = threadIdx.x & 31;
    int node = blockIdx.x * 8 + warp;
    if (node >= NND) return;
    int beg = g_rowstart[node];
    int end = g_rowstart[node + 1];
    float a[8] = {0.f, 0.f, 0.f, 0.f, 0.f, 0.f, 0.f, 0.f};
    int e = beg;
    if (LAYER == 1) {
        const float* __restrict__ X = Xarg;
        for (; e + 1 < end; e += 2) {
            int s0 = g_srcs[e], s1 = g_srcs[e + 1];
            float4 v0 = ((const float4*)(X + (size_t)s0 * D))[lane];
            float4 v1 = ((const float4*)(X + (size_t)s1 * D))[lane];
            a[0] += v0.x; a[1] += v0.y; a[2] += v0.z; a[3] += v0.w;
            a[0] += v1.x; a[1] += v1.y; a[2] += v1.z; a[3] += v1.w;
        }
        if (e < end) {
            float4 v0 = ((const float4*)(X + (size_t)g_srcs[e] * D))[lane];
            a[0] += v0.x; a[1] += v0.y; a[2] += v0.z; a[3] += v0.w;
        }
    } else {
        for (; e + 1 < end; e += 2) {
            int s0 = g_srcs[e], s1 = g_srcs[e + 1];
            uint4 u0 = ((const uint4*)(g_h1 + (size_t)s0 * D))[lane];
            uint4 u1 = ((const uint4*)(g_h1 + (size_t)s1 * D))[lane];
            const __half2* p0 = (const __half2*)&u0;
            const __half2* p1 = (const __half2*)&u1;
            #pragma unroll
            for (int q = 0; q < 4; q++) {
                float2 f0 = __half22float2(p0[q]);
                float2 f1 = __half22float2(p1[q]);
                a[2 * q]     += f0.x + f1.x;
                a[2 * q + 1] += f0.y + f1.y;
            }
        }
        if (e < end) {
            uint4 u0 = ((const uint4*)(g_h1 + (size_t)g_srcs[e] * D))[lane];
            const __half2* p0 = (const __half2*)&u0;
            #pragma unroll
            for (int q = 0; q < 4; q++) {
                float2 f0 = __half22float2(p0[q]);
                a[2 * q]     += f0.x;
                a[2 * q + 1] += f0.y;
            }
        }
    }
    float sc = 1.f / fmaxf((float)(end - beg), 1.f);
    if (LAYER == 1) {
        __half h[4], l[4];
        #pragma unroll
        for (int q = 0; q < 4; q++) split_f16(a[q] * sc, h[q], l[q]);
        __half2 hh[2] = { __halves2half2(h[0], h[1]), __halves2half2(h[2], h[3]) };
        __half2 ll[2] = { __halves2half2(l[0], l[1]), __halves2half2(l[2], l[3]) };
        *(uint2*)(g_mhi + (size_t)node * D + lane * 4) = *(uint2*)hh;
        *(uint2*)(g_mlo + (size_t)node * D + lane * 4) = *(uint2*)ll;
    } else {
        __half h[8], l[8];
        #pragma unroll
        for (int q = 0; q < 8; q++) split_f16(a[q] * sc, h[q], l[q]);
        __half2 hh[4], ll[4];
        #pragma unroll
        for (int q = 0; q < 4; q++) {
            hh[q] = __halves2half2(h[2 * q], h[2 * q + 1]);
            ll[q] = __halves2half2(l[2 * q], l[2 * q + 1]);
        }
        *(uint4*)(g_mhi + (size_t)node * D + lane * 8) = *(uint4*)hh;
        *(uint4*)(g_mlo + (size_t)node * D + lane * 8) = *(uint4*)ll;
    }
}

// ------- dual GEMM + bias + relu, fp16 asymmetric-split wmma, cp.async -----
// C = relu(mean@Wl + X@Wr + bias). Per half: A-tiles {hi, lo?} x B single.
// Layer1: halves {mean(2), x(2)}; Layer2: {mean(2), h1(1)}.
// One CTA: 128x256 tile, 512 threads = 16 warps (2x8), warp tile 64x32.
#define LDA 40     // fp16 elems per A row (32 + 8 pad)
#define LDB 264    // fp16 elems per B row (256 + 8 pad)
#define OF_A0 0
#define OF_A1 10240     // 128*40*2
#define OF_B  20480
#define BUFSZ 37376     // + 32*264*2
#define GSMEM (2 * BUFSZ)

template <int LAYER>
__global__ void __launch_bounds__(512) gemm_wmma_kernel(const float* __restrict__ bias) {
    constexpr int K = (LAYER == 1) ? DIN : DH;
    constexpr int CPH = K / 32;
    const __half* A0s[2] = { g_mhi, (LAYER == 1) ? g_xhi : g_h1 };
    const __half* A1s[2] = { g_mlo, (LAYER == 1) ? g_xlo : (const __half*)0 };
    const __half* Bs2[2] = { (LAYER == 1) ? g_w1l : g_w2l,
                             (LAYER == 1) ? g_w1r : g_w2r };

    extern __shared__ char smem[];
    unsigned sb = smem_u32(smem);
    int tid = threadIdx.x;
    int wid = tid >> 5, lane = tid & 31;
    int warpRow = wid >> 3, warpCol = wid & 7;
    int rowBase = blockIdx.x * 128;

    wmma::fragment<wmma::accumulator, 16, 16, 16, float> acc[4][2];
    #pragma unroll
    for (int i = 0; i < 4; i++)
        #pragma unroll
        for (int j = 0; j < 2; j++) wmma::fill_fragment(acc[i][j], 0.f);

    int arow = tid >> 2, ac = (tid & 3) * 8;
    int brow0 = tid >> 5, bc0 = (tid & 31) * 8;
    int brow1 = 16 + (tid >> 5), bc1 = bc0;

    const int total = 2 * CPH;
    auto stage = [&](int s, int buf) {
        int h = s / CPH, k0 = (s % CPH) * 32;
        const __half* A0 = A0s[h];
        const __half* A1 = A1s[h];
        const __half* B  = Bs2[h];
        unsigned base = sb + buf * BUFSZ;
        int gr = rowBase + arow;
        if (gr > NND - 1) gr = NND - 1;          // OOB rows: content discarded
        cp16(base + OF_A0 + arow * (LDA * 2) + ac * 2, A0 + (size_t)gr * K + k0 + ac);
        if (A1)
            cp16(base + OF_A1 + arow * (LDA * 2) + ac * 2, A1 + (size_t)gr * K + k0 + ac);
        cp16(base + OF_B + brow0 * (LDB * 2) + bc0 * 2, B + (size_t)(k0 + brow0) * DH + bc0);
        cp16(base + OF_B + brow1 * (LDB * 2) + bc1 * 2, B + (size_t)(k0 + brow1) * DH + bc1);
        cp_commit();
    };

    stage(0, 0);
    for (int s = 0; s < total; s++) {
        int buf = s & 1;
        if (s + 1 < total) { stage(s + 1, buf ^ 1); cp_wait<1>(); }
        else               { cp_wait<0>(); }
        __syncthreads();
        int h = s / CPH;
        int na = (LAYER == 1) ? 2 : (h == 0 ? 2 : 1);
        const __half* As0 = (const __half*)(smem + buf * BUFSZ + OF_A0);
        const __half* As1 = (const __half*)(smem + buf * BUFSZ + OF_A1);
        const __half* Bsm = (const __half*)(smem + buf * BUFSZ + OF_B);
        #pragma unroll
        for (int kf = 0; kf < 2; kf++) {
            wmma::fragment<wmma::matrix_b, 16, 16, 16, __half, wmma::row_major> bf[2];
            #pragma unroll
            for (int j = 0; j < 2; j++)
                wmma::load_matrix_sync(bf[j], Bsm + (kf * 16) * LDB + warpCol * 32 + j * 16, LDB);
            #pragma unroll
            for (int i = 0; i < 4; i++) {
                wmma::fragment<wmma::matrix_a, 16, 16, 16, __half, wmma::row_major> af0;
                wmma::load_matrix_sync(af0, As0 + (warpRow * 64 + i * 16) * LDA + kf * 16, LDA);
                #pragma unroll
                for (int j = 0; j < 2; j++)
                    wmma::mma_sync(acc[i][j], af0, bf[j], acc[i][j]);
                if (na == 2) {
                    wmma::fragment<wmma::matrix_a, 16, 16, 16, __half, wmma::row_major> af1;
                    wmma::load_matrix_sync(af1, As1 + (warpRow * 64 + i * 16) * LDA + kf * 16, LDA);
                    #pragma unroll
                    for (int j = 0; j < 2; j++)
                        wmma::mma_sync(acc[i][j], af1, bf[j], acc[i][j]);
                }
            }
        }
        __syncthreads();
    }

    // epilogue via per-warp smem staging (aliases buffers; sync'd above)
    float* buf = (float*)(smem) + wid * 256;
    #pragma unroll
    for (int i = 0; i < 4; i++) {
        #pragma unroll
        for (int j = 0; j < 2; j++) {
            wmma::store_matrix_sync(buf, acc[i][j], 16, wmma::mem_row_major);
            __syncwarp();
            #pragma unroll
            for (int e = 0; e < 8; e++) {
                int idx = e * 32 + lane;
                int r = idx >> 4, c = idx & 15;
                int gr = rowBase + warpRow * 64 + i * 16 + r;
                int gc = warpCol * 32 + j * 16 + c;
                if (gr < NND) {
                    float v = buf[r * 16 + c] + bias[gc];
                    v = v > 0.f ? v : 0.f;
                    if (LAYER == 1) {
                        g_h1[(size_t)gr * DH + gc] = __float2half_rn(v);
                    } else {
                        g_h2[(size_t)gr * DH + gc] = v;
                    }
                }
            }
            __syncwarp();
        }
    }
}

// ----------------------- global mean pool (batch sorted) -------------------
__global__ void __launch_bounds__(256) pool_kernel(const void* __restrict__ batch) {
    __shared__ int sbatch[512];
    int base = blockIdx.x * 512;
    int c = threadIdx.x;
    int is64 = g_b64;
    for (int j = threadIdx.x; j < 512; j += 256) {
        int idx = base + j;
        int g = -1;
        if (idx < NND) g = clampi(idx_at(batch, idx, is64), 0, NG - 1);
        sbatch[j] = g;
    }
    __syncthreads();
    float acc = 0.f;
    int cntl = 0;
    int cur = sbatch[0];
    for (int j = 0; j < 512; j++) {
        int g = sbatch[j];
        if (g != cur) {
            if (cur >= 0) {
                atomicAdd(&g_pool[cur * DH + c], acc);
                if (c == 0) atomicAdd(&g_cnt[cur], cntl);
            }
            acc = 0.f; cntl = 0; cur = g;
        }
        if (g < 0) break;
        acc += g_h2[(size_t)(base + j) * DH + c];
        cntl++;
    }
    if (cur >= 0) {
        atomicAdd(&g_pool[cur * DH + c], acc);
        if (c == 0) atomicAdd(&g_cnt[cur], cntl);
    }
}

__global__ void final_kernel(const float* __restrict__ fcW,
                             const float* __restrict__ fcb,
                             float* __restrict__ out) {
    int t = threadIdx.x;
    int g = t >> 4;
    int cls = t & 15;
    float invc = 1.f / fmaxf((float)g_cnt[g], 1.f);
    float sum = fcb[cls];
    for (int k = 0; k < DH; k++)
        sum += g_pool[g * DH + k] * invc * fcW[k * NC + cls];
    out[g * NC + cls] = sum;
}

// -------------------------------- launch -----------------------------------
extern "C" void kernel_launch(void* const* d_in, const int* in_sizes, int n_in,
                              void* d_out, int out_size) {
    const float *x = 0, *W1l = 0, *b1 = 0, *W1r = 0, *W2l = 0, *b2 = 0,
                *W2r = 0, *fcW = 0, *fcb = 0;
    const void *ei = 0, *batch = 0;
    int ei_elems = 2 * NEMAX;
    for (int i = 0; i < n_in; i++) {
        int s = in_sizes[i];
        const void* p = d_in[i];
        if (s == NND * DIN)            { x = (const float*)p; }
        else if (s == 2 * NEMAX)       { ei = p; ei_elems = s; }
        else if (s == NND)             { batch = p; }
        else if (s == DIN * DH)        { if (!W1l) W1l = (const float*)p; else W1r = (const float*)p; }
        else if (s == DH * DH)         { if (!W2l) W2l = (const float*)p; else W2r = (const float*)p; }
        else if (s == DH)              { if (!b1)  b1  = (const float*)p; else b2  = (const float*)p; }
        else if (s == DH * NC)         { fcW = (const float*)p; }
        else if (s == NC)              { fcb = (const float*)p; }
    }
    float* out = (float*)d_out;
    int E = ei_elems / 2;
    if (E > NEMAX) E = NEMAX;

    cudaFuncSetAttribute(gemm_wmma_kernel<1>, cudaFuncAttributeMaxDynamicSharedMemorySize, GSMEM);
    cudaFuncSetAttribute(gemm_wmma_kernel<2>, cudaFuncAttributeMaxDynamicSharedMemorySize, GSMEM);

    detect_kernel<<<1, 32>>>(ei, batch, E, NND);

    zero_kernel<<<(NND + 255) / 256, 256>>>();
    count_deg_kernel<<<(E + 255) / 256, 256>>>(ei, E);
    scan_local_kernel<<<NCHUNK, 1024>>>();
    scan_chunks_kernel<<<1, 32>>>();
    add_offsets_kernel<<<(NND + 255) / 256, 256>>>();
    fill_csr_kernel<<<(E + 255) / 256, 256>>>(ei, E);

    convert_x_kernel<<<(NND * DIN / 4 + 255) / 256, 256>>>(x);
    convert_w_kernel<1><<<(DIN * DH + 255) / 256, 256>>>(W1l, W1r);
    convert_w_kernel<2><<<(DH * DH + 255) / 256, 256>>>(W2l, W2r);

    int ggrid = (NND + 127) / 128;   // 782

    // layer 1
    agg_mean_kernel<1><<<(NND + 7) / 8, 256>>>(x);
    gemm_wmma_kernel<1><<<ggrid, 512, GSMEM>>>(b1);

    // layer 2
    agg_mean_kernel<2><<<(NND + 7) / 8, 256>>>(x);
    gemm_wmma_kernel<2><<<ggrid, 512, GSMEM>>>(b2);

    pool_kernel<<<(NND + 511) / 512, 256>>>(batch);
    final_kernel<<<1, 1024>>>(fcW, fcb, out);
}